// round 5
// baseline (speedup 1.0000x reference)
#include <cuda_runtime.h>

#define BATCH   8
#define NPTS    4096
#define NPOINTS 1024
#define NSAMPLE 32
#define PIN_A   68    // padded row for 67-ch buffer
#define PIN_B   132   // padded row for 128-ch buffer

// scratch (allocation-free rule: __device__ globals)
__device__ int g_group_idx[BATCH * NPOINTS * NSAMPLE];

// Non-FMA squared distance matching XLA's unfused mul/add reduce ((d0^2+d1^2)+d2^2)
__device__ __forceinline__ float sqd_nofma(float x, float y, float z,
                                           float cx, float cy, float cz) {
    float dx = x - cx, dy = y - cy, dz = z - cz;
    return __fadd_rn(__fadd_rn(__fmul_rn(dx, dx), __fmul_rn(dy, dy)), __fmul_rn(dz, dz));
}

// ---------------------------------------------------------------------------
// Kernel 1: farthest point sampling. One block per batch, 512 threads,
// 8 points per thread. Per step:
//   - update pd[] (exact XLA rounding), fmax TREE (3 levels) for best dist,
//     parallel index recovery imin(pd==bd ? n : BIG) -> lowest index tie-break
//   - pack u64 key (bits(dist)<<32 | (4095-n)), 5-round warp shuffle max
//   - leaders STS to parity-selected 16-slot bank, ONE barrier,
//     every warp redundantly reduces the 16 keys (4 rounds) and LDGs the
//     centroid itself (uniform, L1-resident) -> no 2nd barrier.
// ---------------------------------------------------------------------------
__global__ __launch_bounds__(512) void fps_kernel(const float* __restrict__ xyz,
                                                  float* __restrict__ new_xyz) {
    const int b   = blockIdx.x;
    const int tid = threadIdx.x;
    const int lane = tid & 31;
    const float* base = xyz + (size_t)b * NPTS * 3;

    float px[8], py[8], pz[8], pd[8];
#pragma unroll
    for (int p = 0; p < 8; ++p) {
        int n = tid + p * 512;
        px[p] = base[n * 3 + 0];
        py[p] = base[n * 3 + 1];
        pz[p] = base[n * 3 + 2];
        pd[p] = 1e10f;
    }

    __shared__ unsigned long long sWarp[32];   // two ping-pong banks of 16

    float cx = __ldg(base + 0), cy = __ldg(base + 1), cz = __ldg(base + 2);
    if (tid == 0) {
        float* o = new_xyz + (size_t)b * NPOINTS * 3;
        o[0] = cx; o[1] = cy; o[2] = cz;
    }

    int bank = 0;
    for (int t = 1; t < NPOINTS; ++t) {
        // ---- distance update (exact) ----
#pragma unroll
        for (int p = 0; p < 8; ++p)
            pd[p] = fminf(pd[p], sqd_nofma(px[p], py[p], pz[p], cx, cy, cz));

        // ---- fmax tree (3 dependent levels instead of 8-deep chain) ----
        float m0 = fmaxf(pd[0], pd[1]);
        float m1 = fmaxf(pd[2], pd[3]);
        float m2 = fmaxf(pd[4], pd[5]);
        float m3 = fmaxf(pd[6], pd[7]);
        float m01 = fmaxf(m0, m1);
        float m23 = fmaxf(m2, m3);
        const float bd = fmaxf(m01, m23);

        // ---- parallel index recovery: lowest n with pd==bd ----
        int bi = 0x7fffffff;
#pragma unroll
        for (int p = 0; p < 8; ++p)
            bi = min(bi, (pd[p] == bd) ? (tid + p * 512) : 0x7fffffff);

        unsigned long long key =
            ((unsigned long long)__float_as_uint(bd) << 32) |
            (unsigned long long)(unsigned)(4095 - bi);
#pragma unroll
        for (int o = 16; o; o >>= 1) {
            unsigned long long ok = __shfl_xor_sync(0xffffffffu, key, o);
            key = (ok > key) ? ok : key;
        }
        if (lane == 0) sWarp[bank * 16 + (tid >> 5)] = key;
        __syncthreads();

        // ---- every warp redundantly combines the 16 warp keys ----
        unsigned long long k = sWarp[bank * 16 + (lane & 15)];
#pragma unroll
        for (int o = 8; o; o >>= 1) {
            unsigned long long ok = __shfl_xor_sync(0xffffffffu, k, o);
            k = (ok > k) ? ok : k;
        }
        const int idx = 4095 - (int)(unsigned)(k & 0xffffffffull);
        cx = __ldg(base + idx * 3 + 0);   // uniform broadcast, L1-resident
        cy = __ldg(base + idx * 3 + 1);
        cz = __ldg(base + idx * 3 + 2);
        if (tid == 0) {
            float* o = new_xyz + ((size_t)b * NPOINTS + t) * 3;
            o[0] = cx; o[1] = cy; o[2] = cz;
        }
        bank ^= 1;   // step t+1 leaders write the other bank: no 2nd barrier needed
    }
}

// ---------------------------------------------------------------------------
// Kernel 2: ball query. Grid (S/8, B), 256 threads: 8 warps = 8 query points.
// ---------------------------------------------------------------------------
__global__ __launch_bounds__(256) void ball_kernel(const float* __restrict__ xyz,
                                                   const float* __restrict__ new_xyz) {
    extern __shared__ float sxyz[];  // 4096*3 floats = 48 KB
    const int b = blockIdx.y;
    const float* base = xyz + (size_t)b * NPTS * 3;
    for (int i = threadIdx.x; i < NPTS * 3 / 4; i += 256)
        ((float4*)sxyz)[i] = ((const float4*)base)[i];
    __syncthreads();

    const int warp = threadIdx.x >> 5;
    const int lane = threadIdx.x & 31;
    const int s    = blockIdx.x * 8 + warp;

    const float* c = new_xyz + ((size_t)b * NPOINTS + s) * 3;
    const float cx = c[0], cy = c[1], cz = c[2];
    const float R2 = (float)(0.2 * 0.2);

    int* out  = g_group_idx + ((size_t)(b * NPOINTS + s)) * NSAMPLE;
    int cnt = 0, first = -1;
    for (int r = 0; r < NPTS / 32; ++r) {
        int n = r * 32 + lane;
        float d = sqd_nofma(sxyz[n * 3], sxyz[n * 3 + 1], sxyz[n * 3 + 2], cx, cy, cz);
        bool ok = !(d > R2);
        unsigned m = __ballot_sync(0xffffffffu, ok);
        if (first < 0 && m) first = r * 32 + (__ffs(m) - 1);
        if (ok) {
            int pos = cnt + __popc(m & ((1u << lane) - 1u));
            if (pos < NSAMPLE) out[pos] = n;
        }
        cnt += __popc(m);
        if (cnt >= NSAMPLE) break;
    }
    if (cnt < NSAMPLE && lane >= cnt && lane < NSAMPLE) out[lane] = first;
}

// ---------------------------------------------------------------------------
// Kernel 3: gather + MLP(67->64->64->128, LN+ReLU each) + max over samples.
// ---------------------------------------------------------------------------
template <int CIN, int COUT, int PIN, int POUT>
__device__ __forceinline__ void gemm_tile(const float* in_s,
                                          const float* __restrict__ W,
                                          const float* __restrict__ bias,
                                          float* out_s, int tid) {
    const int r = tid & 7;    // samples r, r+8, r+16, r+24
    const int c = tid >> 3;   // output column group 0..15
    constexpr int JW = COUT / 16;
    float acc[4][JW];
#pragma unroll
    for (int m = 0; m < 4; ++m)
#pragma unroll
        for (int j = 0; j < JW; ++j) acc[m][j] = 0.0f;

    const float* wbase = W + c * JW;
    constexpr int CMAIN = CIN & ~3;

    for (int i = 0; i < CMAIN; i += 4) {
        float4 a0 = *(const float4*)(in_s + (r + 0)  * PIN + i);
        float4 a1 = *(const float4*)(in_s + (r + 8)  * PIN + i);
        float4 a2 = *(const float4*)(in_s + (r + 16) * PIN + i);
        float4 a3 = *(const float4*)(in_s + (r + 24) * PIN + i);
        const float av[4][4] = {
            {a0.x, a1.x, a2.x, a3.x},
            {a0.y, a1.y, a2.y, a3.y},
            {a0.z, a1.z, a2.z, a3.z},
            {a0.w, a1.w, a2.w, a3.w}};
#pragma unroll
        for (int u = 0; u < 4; ++u) {
            const float4* wp = (const float4*)(wbase + (i + u) * COUT);
#pragma unroll
            for (int v = 0; v < JW / 4; ++v) {
                float4 w = __ldg(wp + v);
#pragma unroll
                for (int m = 0; m < 4; ++m) {
                    acc[m][v * 4 + 0] = fmaf(av[u][m], w.x, acc[m][v * 4 + 0]);
                    acc[m][v * 4 + 1] = fmaf(av[u][m], w.y, acc[m][v * 4 + 1]);
                    acc[m][v * 4 + 2] = fmaf(av[u][m], w.z, acc[m][v * 4 + 2]);
                    acc[m][v * 4 + 3] = fmaf(av[u][m], w.w, acc[m][v * 4 + 3]);
                }
            }
        }
    }
    // remainder channels (layer 1: i = 64..66)
    for (int i = CMAIN; i < CIN; ++i) {
        float s0 = in_s[(r + 0)  * PIN + i];
        float s1 = in_s[(r + 8)  * PIN + i];
        float s2 = in_s[(r + 16) * PIN + i];
        float s3 = in_s[(r + 24) * PIN + i];
        const float4* wp = (const float4*)(wbase + i * COUT);
#pragma unroll
        for (int v = 0; v < JW / 4; ++v) {
            float4 w = __ldg(wp + v);
            acc[0][v * 4 + 0] = fmaf(s0, w.x, acc[0][v * 4 + 0]);
            acc[0][v * 4 + 1] = fmaf(s0, w.y, acc[0][v * 4 + 1]);
            acc[0][v * 4 + 2] = fmaf(s0, w.z, acc[0][v * 4 + 2]);
            acc[0][v * 4 + 3] = fmaf(s0, w.w, acc[0][v * 4 + 3]);
            acc[1][v * 4 + 0] = fmaf(s1, w.x, acc[1][v * 4 + 0]);
            acc[1][v * 4 + 1] = fmaf(s1, w.y, acc[1][v * 4 + 1]);
            acc[1][v * 4 + 2] = fmaf(s1, w.z, acc[1][v * 4 + 2]);
            acc[1][v * 4 + 3] = fmaf(s1, w.w, acc[1][v * 4 + 3]);
            acc[2][v * 4 + 0] = fmaf(s2, w.x, acc[2][v * 4 + 0]);
            acc[2][v * 4 + 1] = fmaf(s2, w.y, acc[2][v * 4 + 1]);
            acc[2][v * 4 + 2] = fmaf(s2, w.z, acc[2][v * 4 + 2]);
            acc[2][v * 4 + 3] = fmaf(s2, w.w, acc[2][v * 4 + 3]);
            acc[3][v * 4 + 0] = fmaf(s3, w.x, acc[3][v * 4 + 0]);
            acc[3][v * 4 + 1] = fmaf(s3, w.y, acc[3][v * 4 + 1]);
            acc[3][v * 4 + 2] = fmaf(s3, w.z, acc[3][v * 4 + 2]);
            acc[3][v * 4 + 3] = fmaf(s3, w.w, acc[3][v * 4 + 3]);
        }
    }
#pragma unroll
    for (int j = 0; j < JW; ++j) {
        float bj = __ldg(bias + c * JW + j);
#pragma unroll
        for (int m = 0; m < 4; ++m)
            out_s[(r + 8 * m) * POUT + c * JW + j] = acc[m][j] + bj;
    }
}

template <int C, int P>
__device__ __forceinline__ void ln_relu(float* buf,
                                        const float* __restrict__ g,
                                        const float* __restrict__ be, int tid) {
    const int s = tid >> 2, q = tid & 3;  // 4 threads per sample
    constexpr int SPAN = C / 4;
    float* row = buf + s * P + q * SPAN;
    float vals[SPAN];
    float sum = 0.0f;
#pragma unroll
    for (int j = 0; j < SPAN; ++j) { vals[j] = row[j]; sum += vals[j]; }
    sum += __shfl_xor_sync(0xffffffffu, sum, 1);
    sum += __shfl_xor_sync(0xffffffffu, sum, 2);
    const float mu = sum * (1.0f / C);
    float sq = 0.0f;
#pragma unroll
    for (int j = 0; j < SPAN; ++j) { float d = vals[j] - mu; sq += d * d; }
    sq += __shfl_xor_sync(0xffffffffu, sq, 1);
    sq += __shfl_xor_sync(0xffffffffu, sq, 2);
    const float inv = rsqrtf(sq * (1.0f / C) + 1e-5f);
#pragma unroll
    for (int j = 0; j < SPAN; ++j) {
        int jj = q * SPAN + j;
        float v = (vals[j] - mu) * inv * __ldg(g + jj) + __ldg(be + jj);
        row[j] = fmaxf(v, 0.0f);
    }
}

__global__ __launch_bounds__(128) void mlp_kernel(
    const float* __restrict__ xyz, const float* __restrict__ points,
    const float* __restrict__ new_xyz,
    const float* __restrict__ W1, const float* __restrict__ b1,
    const float* __restrict__ g1, const float* __restrict__ be1,
    const float* __restrict__ W2, const float* __restrict__ b2,
    const float* __restrict__ g2, const float* __restrict__ be2,
    const float* __restrict__ W3, const float* __restrict__ b3,
    const float* __restrict__ g3, const float* __restrict__ be3,
    float* __restrict__ new_points) {
    __shared__ float bufA[32 * PIN_A];
    __shared__ float bufB[32 * PIN_B];
    __shared__ int   sIdx[32];
    __shared__ float sCen[3];

    const int pair = blockIdx.x;        // b*1024 + s
    const int b    = pair >> 10;
    const int tid  = threadIdx.x;

    if (tid < 32) sIdx[tid] = g_group_idx[pair * NSAMPLE + tid];
    if (tid < 3)  sCen[tid] = new_xyz[(size_t)pair * 3 + tid];
    __syncthreads();

    // gather: 4 threads per sample; 67 channels = [xyz-offset(3), points(64)]
    {
        const int k = tid >> 2, q = tid & 3;
        const int n = sIdx[k];
        const float4* prow = (const float4*)(points + ((size_t)b * NPTS + n) * 64) + q * 4;
        float* dst = bufA + k * PIN_A + 3 + q * 16;
#pragma unroll
        for (int v = 0; v < 4; ++v) {
            float4 f = __ldg(prow + v);
            dst[v * 4 + 0] = f.x;
            dst[v * 4 + 1] = f.y;
            dst[v * 4 + 2] = f.z;
            dst[v * 4 + 3] = f.w;
        }
        if (q == 0) {
            const float* xr = xyz + ((size_t)b * NPTS + n) * 3;
            bufA[k * PIN_A + 0] = xr[0] - sCen[0];
            bufA[k * PIN_A + 1] = xr[1] - sCen[1];
            bufA[k * PIN_A + 2] = xr[2] - sCen[2];
        }
    }
    __syncthreads();

    gemm_tile<67, 64, PIN_A, PIN_B>(bufA, W1, b1, bufB, tid);
    __syncthreads();
    ln_relu<64, PIN_B>(bufB, g1, be1, tid);
    __syncthreads();

    gemm_tile<64, 64, PIN_B, PIN_A>(bufB, W2, b2, bufA, tid);
    __syncthreads();
    ln_relu<64, PIN_A>(bufA, g2, be2, tid);
    __syncthreads();

    gemm_tile<64, 128, PIN_A, PIN_B>(bufA, W3, b3, bufB, tid);
    __syncthreads();
    ln_relu<128, PIN_B>(bufB, g3, be3, tid);
    __syncthreads();

    // max over the 32 group samples; relu outputs >= 0 so init 0 is exact
    {
        const int j = tid;
        float m = 0.0f;
#pragma unroll 8
        for (int k = 0; k < 32; ++k) m = fmaxf(m, bufB[k * PIN_B + j]);
        new_points[(size_t)pair * 128 + j] = m;
    }
}

// ---------------------------------------------------------------------------
extern "C" void kernel_launch(void* const* d_in, const int* in_sizes, int n_in,
                              void* d_out, int out_size) {
    (void)in_sizes; (void)n_in; (void)out_size;
    const float* xyz    = (const float*)d_in[0];
    const float* points = (const float*)d_in[1];
    const float* W1  = (const float*)d_in[2];
    const float* b1  = (const float*)d_in[3];
    const float* g1  = (const float*)d_in[4];
    const float* be1 = (const float*)d_in[5];
    const float* W2  = (const float*)d_in[6];
    const float* b2  = (const float*)d_in[7];
    const float* g2  = (const float*)d_in[8];
    const float* be2 = (const float*)d_in[9];
    const float* W3  = (const float*)d_in[10];
    const float* b3  = (const float*)d_in[11];
    const float* g3  = (const float*)d_in[12];
    const float* be3 = (const float*)d_in[13];

    float* out        = (float*)d_out;
    float* new_xyz    = out;                          // [8,1024,3]
    float* new_points = out + BATCH * NPOINTS * 3;    // [8,1024,128]

    fps_kernel<<<BATCH, 512>>>(xyz, new_xyz);
    ball_kernel<<<dim3(NPOINTS / 8, BATCH), 256, NPTS * 3 * sizeof(float)>>>(xyz, new_xyz);
    mlp_kernel<<<BATCH * NPOINTS, 128>>>(xyz, points, new_xyz,
                                         W1, b1, g1, be1,
                                         W2, b2, g2, be2,
                                         W3, b3, g3, be3,
                                         new_points);
}

// round 6
// speedup vs baseline: 1.1985x; 1.1985x over previous
#include <cuda_runtime.h>

#define BATCH   8
#define NPTS    4096
#define NPOINTS 1024
#define NSAMPLE 32
#define PIN_A   68    // padded row for 67-ch buffer
#define PIN_B   132   // padded row for 128-ch buffer

// scratch (allocation-free rule: __device__ globals)
__device__ int g_group_idx[BATCH * NPOINTS * NSAMPLE];

// Non-FMA squared distance matching XLA's unfused mul/add reduce ((d0^2+d1^2)+d2^2)
__device__ __forceinline__ float sqd_nofma(float x, float y, float z,
                                           float cx, float cy, float cz) {
    float dx = x - cx, dy = y - cy, dz = z - cz;
    return __fadd_rn(__fadd_rn(__fmul_rn(dx, dx), __fmul_rn(dy, dy)), __fmul_rn(dz, dz));
}

// ---------------------------------------------------------------------------
// Kernel 1: farthest point sampling. One block per batch, 512 threads,
// 8 points per thread. Issue-count-optimized reduction tail:
//   - fmax tree + parallel lowest-index recovery (exact jnp.argmax tie-break)
//   - warp combine:   REDUX.SYNC.UMAX on dist bits (dist>=0 -> order-safe),
//                     then REDUX.SYNC.UMIN on candidate index
//   - block combine:  leaders STS {distbits, idx} to parity ping-pong bank,
//                     ONE barrier, every warp LDS.64 + same redux pair,
//                     then uniform LDG of the centroid.
// ---------------------------------------------------------------------------
__global__ __launch_bounds__(512) void fps_kernel(const float* __restrict__ xyz,
                                                  float* __restrict__ new_xyz) {
    const int b    = blockIdx.x;
    const int tid  = threadIdx.x;
    const int lane = tid & 31;
    const float* base = xyz + (size_t)b * NPTS * 3;

    float px[8], py[8], pz[8], pd[8];
#pragma unroll
    for (int p = 0; p < 8; ++p) {
        int n = tid + p * 512;
        px[p] = base[n * 3 + 0];
        py[p] = base[n * 3 + 1];
        pz[p] = base[n * 3 + 2];
        pd[p] = 1e10f;
    }

    __shared__ uint2 sWarp[32];   // two ping-pong banks of 16: {distbits, idx}

    float cx = __ldg(base + 0), cy = __ldg(base + 1), cz = __ldg(base + 2);
    if (tid == 0) {
        float* o = new_xyz + (size_t)b * NPOINTS * 3;
        o[0] = cx; o[1] = cy; o[2] = cz;
    }

    int bank = 0;
    for (int t = 1; t < NPOINTS; ++t) {
        // ---- distance update (exact XLA rounding) ----
#pragma unroll
        for (int p = 0; p < 8; ++p)
            pd[p] = fminf(pd[p], sqd_nofma(px[p], py[p], pz[p], cx, cy, cz));

        // ---- fmax tree ----
        float m0 = fmaxf(pd[0], pd[1]);
        float m1 = fmaxf(pd[2], pd[3]);
        float m2 = fmaxf(pd[4], pd[5]);
        float m3 = fmaxf(pd[6], pd[7]);
        const float bd = fmaxf(fmaxf(m0, m1), fmaxf(m2, m3));

        // ---- parallel lowest-index recovery ----
        int bi = 0x7fffffff;
#pragma unroll
        for (int p = 0; p < 8; ++p)
            bi = min(bi, (pd[p] == bd) ? (tid + p * 512) : 0x7fffffff);

        // ---- warp combine via redux (dist >= 0 -> float order == uint order) ----
        const unsigned bdb = __float_as_uint(bd);
        const unsigned wd  = __reduce_max_sync(0xffffffffu, bdb);
        const unsigned wi  = __reduce_min_sync(0xffffffffu,
                                (bdb == wd) ? (unsigned)bi : 0xffffffffu);
        if (lane == 0) sWarp[bank * 16 + (tid >> 5)] = make_uint2(wd, wi);
        __syncthreads();

        // ---- every warp redundantly combines the 16 warp keys ----
        const uint2 k  = sWarp[bank * 16 + (lane & 15)];
        const unsigned gd = __reduce_max_sync(0xffffffffu, k.x);
        const unsigned gi = __reduce_min_sync(0xffffffffu,
                                (k.x == gd) ? k.y : 0xffffffffu);
        const int idx = (int)gi;
        cx = __ldg(base + idx * 3 + 0);   // uniform broadcast, L1-resident
        cy = __ldg(base + idx * 3 + 1);
        cz = __ldg(base + idx * 3 + 2);
        if (tid == 0) {
            float* o = new_xyz + ((size_t)b * NPOINTS + t) * 3;
            o[0] = cx; o[1] = cy; o[2] = cz;
        }
        bank ^= 1;   // next step's leaders write the other bank: no 2nd barrier
    }
}

// ---------------------------------------------------------------------------
// Kernel 2: ball query. Grid (S/8, B), 256 threads: 8 warps = 8 query points.
// ---------------------------------------------------------------------------
__global__ __launch_bounds__(256) void ball_kernel(const float* __restrict__ xyz,
                                                   const float* __restrict__ new_xyz) {
    extern __shared__ float sxyz[];  // 4096*3 floats = 48 KB
    const int b = blockIdx.y;
    const float* base = xyz + (size_t)b * NPTS * 3;
    for (int i = threadIdx.x; i < NPTS * 3 / 4; i += 256)
        ((float4*)sxyz)[i] = ((const float4*)base)[i];
    __syncthreads();

    const int warp = threadIdx.x >> 5;
    const int lane = threadIdx.x & 31;
    const int s    = blockIdx.x * 8 + warp;

    const float* c = new_xyz + ((size_t)b * NPOINTS + s) * 3;
    const float cx = c[0], cy = c[1], cz = c[2];
    const float R2 = (float)(0.2 * 0.2);

    int* out  = g_group_idx + ((size_t)(b * NPOINTS + s)) * NSAMPLE;
    int cnt = 0, first = -1;
    for (int r = 0; r < NPTS / 32; ++r) {
        int n = r * 32 + lane;
        float d = sqd_nofma(sxyz[n * 3], sxyz[n * 3 + 1], sxyz[n * 3 + 2], cx, cy, cz);
        bool ok = !(d > R2);
        unsigned m = __ballot_sync(0xffffffffu, ok);
        if (first < 0 && m) first = r * 32 + (__ffs(m) - 1);
        if (ok) {
            int pos = cnt + __popc(m & ((1u << lane) - 1u));
            if (pos < NSAMPLE) out[pos] = n;
        }
        cnt += __popc(m);
        if (cnt >= NSAMPLE) break;
    }
    if (cnt < NSAMPLE && lane >= cnt && lane < NSAMPLE) out[lane] = first;
}

// ---------------------------------------------------------------------------
// Kernel 3: gather + MLP(67->64->64->128, LN+ReLU each) + max over samples.
// ---------------------------------------------------------------------------
template <int CIN, int COUT, int PIN, int POUT>
__device__ __forceinline__ void gemm_tile(const float* in_s,
                                          const float* __restrict__ W,
                                          const float* __restrict__ bias,
                                          float* out_s, int tid) {
    const int r = tid & 7;    // samples r, r+8, r+16, r+24
    const int c = tid >> 3;   // output column group 0..15
    constexpr int JW = COUT / 16;
    float acc[4][JW];
#pragma unroll
    for (int m = 0; m < 4; ++m)
#pragma unroll
        for (int j = 0; j < JW; ++j) acc[m][j] = 0.0f;

    const float* wbase = W + c * JW;
    constexpr int CMAIN = CIN & ~3;

    for (int i = 0; i < CMAIN; i += 4) {
        float4 a0 = *(const float4*)(in_s + (r + 0)  * PIN + i);
        float4 a1 = *(const float4*)(in_s + (r + 8)  * PIN + i);
        float4 a2 = *(const float4*)(in_s + (r + 16) * PIN + i);
        float4 a3 = *(const float4*)(in_s + (r + 24) * PIN + i);
        const float av[4][4] = {
            {a0.x, a1.x, a2.x, a3.x},
            {a0.y, a1.y, a2.y, a3.y},
            {a0.z, a1.z, a2.z, a3.z},
            {a0.w, a1.w, a2.w, a3.w}};
#pragma unroll
        for (int u = 0; u < 4; ++u) {
            const float4* wp = (const float4*)(wbase + (i + u) * COUT);
#pragma unroll
            for (int v = 0; v < JW / 4; ++v) {
                float4 w = __ldg(wp + v);
#pragma unroll
                for (int m = 0; m < 4; ++m) {
                    acc[m][v * 4 + 0] = fmaf(av[u][m], w.x, acc[m][v * 4 + 0]);
                    acc[m][v * 4 + 1] = fmaf(av[u][m], w.y, acc[m][v * 4 + 1]);
                    acc[m][v * 4 + 2] = fmaf(av[u][m], w.z, acc[m][v * 4 + 2]);
                    acc[m][v * 4 + 3] = fmaf(av[u][m], w.w, acc[m][v * 4 + 3]);
                }
            }
        }
    }
    // remainder channels (layer 1: i = 64..66)
    for (int i = CMAIN; i < CIN; ++i) {
        float s0 = in_s[(r + 0)  * PIN + i];
        float s1 = in_s[(r + 8)  * PIN + i];
        float s2 = in_s[(r + 16) * PIN + i];
        float s3 = in_s[(r + 24) * PIN + i];
        const float4* wp = (const float4*)(wbase + i * COUT);
#pragma unroll
        for (int v = 0; v < JW / 4; ++v) {
            float4 w = __ldg(wp + v);
            acc[0][v * 4 + 0] = fmaf(s0, w.x, acc[0][v * 4 + 0]);
            acc[0][v * 4 + 1] = fmaf(s0, w.y, acc[0][v * 4 + 1]);
            acc[0][v * 4 + 2] = fmaf(s0, w.z, acc[0][v * 4 + 2]);
            acc[0][v * 4 + 3] = fmaf(s0, w.w, acc[0][v * 4 + 3]);
            acc[1][v * 4 + 0] = fmaf(s1, w.x, acc[1][v * 4 + 0]);
            acc[1][v * 4 + 1] = fmaf(s1, w.y, acc[1][v * 4 + 1]);
            acc[1][v * 4 + 2] = fmaf(s1, w.z, acc[1][v * 4 + 2]);
            acc[1][v * 4 + 3] = fmaf(s1, w.w, acc[1][v * 4 + 3]);
            acc[2][v * 4 + 0] = fmaf(s2, w.x, acc[2][v * 4 + 0]);
            acc[2][v * 4 + 1] = fmaf(s2, w.y, acc[2][v * 4 + 1]);
            acc[2][v * 4 + 2] = fmaf(s2, w.z, acc[2][v * 4 + 2]);
            acc[2][v * 4 + 3] = fmaf(s2, w.w, acc[2][v * 4 + 3]);
            acc[3][v * 4 + 0] = fmaf(s3, w.x, acc[3][v * 4 + 0]);
            acc[3][v * 4 + 1] = fmaf(s3, w.y, acc[3][v * 4 + 1]);
            acc[3][v * 4 + 2] = fmaf(s3, w.z, acc[3][v * 4 + 2]);
            acc[3][v * 4 + 3] = fmaf(s3, w.w, acc[3][v * 4 + 3]);
        }
    }
#pragma unroll
    for (int j = 0; j < JW; ++j) {
        float bj = __ldg(bias + c * JW + j);
#pragma unroll
        for (int m = 0; m < 4; ++m)
            out_s[(r + 8 * m) * POUT + c * JW + j] = acc[m][j] + bj;
    }
}

template <int C, int P>
__device__ __forceinline__ void ln_relu(float* buf,
                                        const float* __restrict__ g,
                                        const float* __restrict__ be, int tid) {
    const int s = tid >> 2, q = tid & 3;  // 4 threads per sample
    constexpr int SPAN = C / 4;
    float* row = buf + s * P + q * SPAN;
    float vals[SPAN];
    float sum = 0.0f;
#pragma unroll
    for (int j = 0; j < SPAN; ++j) { vals[j] = row[j]; sum += vals[j]; }
    sum += __shfl_xor_sync(0xffffffffu, sum, 1);
    sum += __shfl_xor_sync(0xffffffffu, sum, 2);
    const float mu = sum * (1.0f / C);
    float sq = 0.0f;
#pragma unroll
    for (int j = 0; j < SPAN; ++j) { float d = vals[j] - mu; sq += d * d; }
    sq += __shfl_xor_sync(0xffffffffu, sq, 1);
    sq += __shfl_xor_sync(0xffffffffu, sq, 2);
    const float inv = rsqrtf(sq * (1.0f / C) + 1e-5f);
#pragma unroll
    for (int j = 0; j < SPAN; ++j) {
        int jj = q * SPAN + j;
        float v = (vals[j] - mu) * inv * __ldg(g + jj) + __ldg(be + jj);
        row[j] = fmaxf(v, 0.0f);
    }
}

__global__ __launch_bounds__(128) void mlp_kernel(
    const float* __restrict__ xyz, const float* __restrict__ points,
    const float* __restrict__ new_xyz,
    const float* __restrict__ W1, const float* __restrict__ b1,
    const float* __restrict__ g1, const float* __restrict__ be1,
    const float* __restrict__ W2, const float* __restrict__ b2,
    const float* __restrict__ g2, const float* __restrict__ be2,
    const float* __restrict__ W3, const float* __restrict__ b3,
    const float* __restrict__ g3, const float* __restrict__ be3,
    float* __restrict__ new_points) {
    __shared__ float bufA[32 * PIN_A];
    __shared__ float bufB[32 * PIN_B];
    __shared__ int   sIdx[32];
    __shared__ float sCen[3];

    const int pair = blockIdx.x;        // b*1024 + s
    const int b    = pair >> 10;
    const int tid  = threadIdx.x;

    if (tid < 32) sIdx[tid] = g_group_idx[pair * NSAMPLE + tid];
    if (tid < 3)  sCen[tid] = new_xyz[(size_t)pair * 3 + tid];
    __syncthreads();

    // gather: 4 threads per sample; 67 channels = [xyz-offset(3), points(64)]
    {
        const int k = tid >> 2, q = tid & 3;
        const int n = sIdx[k];
        const float4* prow = (const float4*)(points + ((size_t)b * NPTS + n) * 64) + q * 4;
        float* dst = bufA + k * PIN_A + 3 + q * 16;
#pragma unroll
        for (int v = 0; v < 4; ++v) {
            float4 f = __ldg(prow + v);
            dst[v * 4 + 0] = f.x;
            dst[v * 4 + 1] = f.y;
            dst[v * 4 + 2] = f.z;
            dst[v * 4 + 3] = f.w;
        }
        if (q == 0) {
            const float* xr = xyz + ((size_t)b * NPTS + n) * 3;
            bufA[k * PIN_A + 0] = xr[0] - sCen[0];
            bufA[k * PIN_A + 1] = xr[1] - sCen[1];
            bufA[k * PIN_A + 2] = xr[2] - sCen[2];
        }
    }
    __syncthreads();

    gemm_tile<67, 64, PIN_A, PIN_B>(bufA, W1, b1, bufB, tid);
    __syncthreads();
    ln_relu<64, PIN_B>(bufB, g1, be1, tid);
    __syncthreads();

    gemm_tile<64, 64, PIN_B, PIN_A>(bufB, W2, b2, bufA, tid);
    __syncthreads();
    ln_relu<64, PIN_A>(bufA, g2, be2, tid);
    __syncthreads();

    gemm_tile<64, 128, PIN_A, PIN_B>(bufA, W3, b3, bufB, tid);
    __syncthreads();
    ln_relu<128, PIN_B>(bufB, g3, be3, tid);
    __syncthreads();

    // max over the 32 group samples; relu outputs >= 0 so init 0 is exact
    {
        const int j = tid;
        float m = 0.0f;
#pragma unroll 8
        for (int k = 0; k < 32; ++k) m = fmaxf(m, bufB[k * PIN_B + j]);
        new_points[(size_t)pair * 128 + j] = m;
    }
}

// ---------------------------------------------------------------------------
extern "C" void kernel_launch(void* const* d_in, const int* in_sizes, int n_in,
                              void* d_out, int out_size) {
    (void)in_sizes; (void)n_in; (void)out_size;
    const float* xyz    = (const float*)d_in[0];
    const float* points = (const float*)d_in[1];
    const float* W1  = (const float*)d_in[2];
    const float* b1  = (const float*)d_in[3];
    const float* g1  = (const float*)d_in[4];
    const float* be1 = (const float*)d_in[5];
    const float* W2  = (const float*)d_in[6];
    const float* b2  = (const float*)d_in[7];
    const float* g2  = (const float*)d_in[8];
    const float* be2 = (const float*)d_in[9];
    const float* W3  = (const float*)d_in[10];
    const float* b3  = (const float*)d_in[11];
    const float* g3  = (const float*)d_in[12];
    const float* be3 = (const float*)d_in[13];

    float* out        = (float*)d_out;
    float* new_xyz    = out;                          // [8,1024,3]
    float* new_points = out + BATCH * NPOINTS * 3;    // [8,1024,128]

    fps_kernel<<<BATCH, 512>>>(xyz, new_xyz);
    ball_kernel<<<dim3(NPOINTS / 8, BATCH), 256, NPTS * 3 * sizeof(float)>>>(xyz, new_xyz);
    mlp_kernel<<<BATCH * NPOINTS, 128>>>(xyz, points, new_xyz,
                                         W1, b1, g1, be1,
                                         W2, b2, g2, be2,
                                         W3, b3, g3, be3,
                                         new_points);
}

// round 7
// speedup vs baseline: 1.3733x; 1.1458x over previous
#include <cuda_runtime.h>

#define BATCH   8
#define NPTS    4096
#define NPOINTS 1024
#define NSAMPLE 32
#define PIN_A   68    // padded row for 67-ch buffer
#define PIN_B   132   // padded row for 128-ch buffer

// scratch (allocation-free rule: __device__ globals)
__device__ int g_group_idx[BATCH * NPOINTS * NSAMPLE];

// Non-FMA squared distance matching XLA's unfused mul/add reduce ((d0^2+d1^2)+d2^2)
__device__ __forceinline__ float sqd_nofma(float x, float y, float z,
                                           float cx, float cy, float cz) {
    float dx = x - cx, dy = y - cy, dz = z - cz;
    return __fadd_rn(__fadd_rn(__fmul_rn(dx, dx), __fmul_rn(dy, dy)), __fmul_rn(dz, dz));
}

// ---- packed f32x2 helpers (Blackwell): per-lane IEEE .rn, bit-identical to scalar ----
__device__ __forceinline__ unsigned long long f2_add(unsigned long long a, unsigned long long b) {
    unsigned long long r;
    asm("add.rn.f32x2 %0, %1, %2;" : "=l"(r) : "l"(a), "l"(b));
    return r;
}
__device__ __forceinline__ unsigned long long f2_mul(unsigned long long a, unsigned long long b) {
    unsigned long long r;
    asm("mul.rn.f32x2 %0, %1, %2;" : "=l"(r) : "l"(a), "l"(b));
    return r;
}
__device__ __forceinline__ unsigned long long f2_pack(float lo, float hi) {
    unsigned long long r;
    asm("mov.b64 %0, {%1, %2};" : "=l"(r) : "f"(lo), "f"(hi));
    return r;
}
__device__ __forceinline__ void f2_unpack(unsigned long long v, float& lo, float& hi) {
    asm("mov.b64 {%0, %1}, %2;" : "=f"(lo), "=f"(hi) : "l"(v));
}

// ---------------------------------------------------------------------------
// Kernel 1: farthest point sampling. One block per batch, 512 threads,
// 8 points per thread, processed as 4 packed f32x2 pairs (pt n & pt n+2048):
// distance update = 8 packed fma-pipe instrs per pair (halves the fma-pipe
// load vs scalar). x + (-c) == x - c exactly; per-lane .rn == scalar FADD/FMUL,
// so selections stay bit-identical to XLA. Warp/block argmax via REDUX.SYNC
// (umax on dist bits, umin on index) with a parity ping-pong smem bank and
// ONE barrier per step.
// ---------------------------------------------------------------------------
__global__ __launch_bounds__(512) void fps_kernel(const float* __restrict__ xyz,
                                                  float* __restrict__ new_xyz) {
    const int b    = blockIdx.x;
    const int tid  = threadIdx.x;
    const int lane = tid & 31;
    const float* base = xyz + (size_t)b * NPTS * 3;

    // packed coords: pair p holds points (tid + p*512, tid + p*512 + 2048)
    unsigned long long pxp[4], pyp[4], pzp[4];
    float pd[8];
#pragma unroll
    for (int p = 0; p < 4; ++p) {
        int n0 = tid + p * 512;
        int n1 = n0 + 2048;
        pxp[p] = f2_pack(base[n0 * 3 + 0], base[n1 * 3 + 0]);
        pyp[p] = f2_pack(base[n0 * 3 + 1], base[n1 * 3 + 1]);
        pzp[p] = f2_pack(base[n0 * 3 + 2], base[n1 * 3 + 2]);
        pd[p] = 1e10f; pd[p + 4] = 1e10f;
    }

    __shared__ uint2 sWarp[32];   // two ping-pong banks of 16: {distbits, idx}

    float cx = __ldg(base + 0), cy = __ldg(base + 1), cz = __ldg(base + 2);
    if (tid == 0) {
        float* o = new_xyz + (size_t)b * NPOINTS * 3;
        o[0] = cx; o[1] = cy; o[2] = cz;
    }

    int bank = 0;
    for (int t = 1; t < NPOINTS; ++t) {
        // ---- packed distance update (exact XLA rounding per lane) ----
        const unsigned long long ncx2 = f2_pack(-cx, -cx);
        const unsigned long long ncy2 = f2_pack(-cy, -cy);
        const unsigned long long ncz2 = f2_pack(-cz, -cz);
#pragma unroll
        for (int p = 0; p < 4; ++p) {
            unsigned long long dx = f2_add(pxp[p], ncx2);
            unsigned long long dy = f2_add(pyp[p], ncy2);
            unsigned long long dz = f2_add(pzp[p], ncz2);
            unsigned long long s  = f2_add(f2_add(f2_mul(dx, dx), f2_mul(dy, dy)),
                                           f2_mul(dz, dz));
            float lo, hi;
            f2_unpack(s, lo, hi);
            pd[p]     = fminf(pd[p],     lo);
            pd[p + 4] = fminf(pd[p + 4], hi);
        }

        // ---- fmax tree ----
        float m0 = fmaxf(pd[0], pd[1]);
        float m1 = fmaxf(pd[2], pd[3]);
        float m2 = fmaxf(pd[4], pd[5]);
        float m3 = fmaxf(pd[6], pd[7]);
        const float bd = fmaxf(fmaxf(m0, m1), fmaxf(m2, m3));

        // ---- parallel lowest-index recovery ----
        // pd[p]   (p<4)  -> n = tid + p*512
        // pd[p+4]        -> n = tid + p*512 + 2048
        int bi = 0x7fffffff;
#pragma unroll
        for (int p = 0; p < 4; ++p)
            bi = min(bi, (pd[p] == bd) ? (tid + p * 512) : 0x7fffffff);
#pragma unroll
        for (int p = 0; p < 4; ++p)
            bi = min(bi, (pd[p + 4] == bd) ? (tid + p * 512 + 2048) : 0x7fffffff);

        // ---- warp combine via redux (dist >= 0 -> float order == uint order) ----
        const unsigned bdb = __float_as_uint(bd);
        const unsigned wd  = __reduce_max_sync(0xffffffffu, bdb);
        const unsigned wi  = __reduce_min_sync(0xffffffffu,
                                (bdb == wd) ? (unsigned)bi : 0xffffffffu);
        if (lane == 0) sWarp[bank * 16 + (tid >> 5)] = make_uint2(wd, wi);
        __syncthreads();

        // ---- every warp redundantly combines the 16 warp keys ----
        const uint2 k  = sWarp[bank * 16 + (lane & 15)];
        const unsigned gd = __reduce_max_sync(0xffffffffu, k.x);
        const unsigned gi = __reduce_min_sync(0xffffffffu,
                                (k.x == gd) ? k.y : 0xffffffffu);
        const int idx = (int)gi;
        cx = __ldg(base + idx * 3 + 0);   // uniform broadcast, L1-resident
        cy = __ldg(base + idx * 3 + 1);
        cz = __ldg(base + idx * 3 + 2);
        if (tid == 0) {
            float* o = new_xyz + ((size_t)b * NPOINTS + t) * 3;
            o[0] = cx; o[1] = cy; o[2] = cz;
        }
        bank ^= 1;   // next step's leaders write the other bank: no 2nd barrier
    }
}

// ---------------------------------------------------------------------------
// Kernel 2: ball query. Grid (S/8, B), 256 threads: 8 warps = 8 query points.
// ---------------------------------------------------------------------------
__global__ __launch_bounds__(256) void ball_kernel(const float* __restrict__ xyz,
                                                   const float* __restrict__ new_xyz) {
    extern __shared__ float sxyz[];  // 4096*3 floats = 48 KB
    const int b = blockIdx.y;
    const float* base = xyz + (size_t)b * NPTS * 3;
    for (int i = threadIdx.x; i < NPTS * 3 / 4; i += 256)
        ((float4*)sxyz)[i] = ((const float4*)base)[i];
    __syncthreads();

    const int warp = threadIdx.x >> 5;
    const int lane = threadIdx.x & 31;
    const int s    = blockIdx.x * 8 + warp;

    const float* c = new_xyz + ((size_t)b * NPOINTS + s) * 3;
    const float cx = c[0], cy = c[1], cz = c[2];
    const float R2 = (float)(0.2 * 0.2);

    int* out  = g_group_idx + ((size_t)(b * NPOINTS + s)) * NSAMPLE;
    int cnt = 0, first = -1;
    for (int r = 0; r < NPTS / 32; ++r) {
        int n = r * 32 + lane;
        float d = sqd_nofma(sxyz[n * 3], sxyz[n * 3 + 1], sxyz[n * 3 + 2], cx, cy, cz);
        bool ok = !(d > R2);
        unsigned m = __ballot_sync(0xffffffffu, ok);
        if (first < 0 && m) first = r * 32 + (__ffs(m) - 1);
        if (ok) {
            int pos = cnt + __popc(m & ((1u << lane) - 1u));
            if (pos < NSAMPLE) out[pos] = n;
        }
        cnt += __popc(m);
        if (cnt >= NSAMPLE) break;
    }
    if (cnt < NSAMPLE && lane >= cnt && lane < NSAMPLE) out[lane] = first;
}

// ---------------------------------------------------------------------------
// Kernel 3: gather + MLP(67->64->64->128, LN+ReLU each) + max over samples.
// ---------------------------------------------------------------------------
template <int CIN, int COUT, int PIN, int POUT>
__device__ __forceinline__ void gemm_tile(const float* in_s,
                                          const float* __restrict__ W,
                                          const float* __restrict__ bias,
                                          float* out_s, int tid) {
    const int r = tid & 7;    // samples r, r+8, r+16, r+24
    const int c = tid >> 3;   // output column group 0..15
    constexpr int JW = COUT / 16;
    float acc[4][JW];
#pragma unroll
    for (int m = 0; m < 4; ++m)
#pragma unroll
        for (int j = 0; j < JW; ++j) acc[m][j] = 0.0f;

    const float* wbase = W + c * JW;
    constexpr int CMAIN = CIN & ~3;

    for (int i = 0; i < CMAIN; i += 4) {
        float4 a0 = *(const float4*)(in_s + (r + 0)  * PIN + i);
        float4 a1 = *(const float4*)(in_s + (r + 8)  * PIN + i);
        float4 a2 = *(const float4*)(in_s + (r + 16) * PIN + i);
        float4 a3 = *(const float4*)(in_s + (r + 24) * PIN + i);
        const float av[4][4] = {
            {a0.x, a1.x, a2.x, a3.x},
            {a0.y, a1.y, a2.y, a3.y},
            {a0.z, a1.z, a2.z, a3.z},
            {a0.w, a1.w, a2.w, a3.w}};
#pragma unroll
        for (int u = 0; u < 4; ++u) {
            const float4* wp = (const float4*)(wbase + (i + u) * COUT);
#pragma unroll
            for (int v = 0; v < JW / 4; ++v) {
                float4 w = __ldg(wp + v);
#pragma unroll
                for (int m = 0; m < 4; ++m) {
                    acc[m][v * 4 + 0] = fmaf(av[u][m], w.x, acc[m][v * 4 + 0]);
                    acc[m][v * 4 + 1] = fmaf(av[u][m], w.y, acc[m][v * 4 + 1]);
                    acc[m][v * 4 + 2] = fmaf(av[u][m], w.z, acc[m][v * 4 + 2]);
                    acc[m][v * 4 + 3] = fmaf(av[u][m], w.w, acc[m][v * 4 + 3]);
                }
            }
        }
    }
    // remainder channels (layer 1: i = 64..66)
    for (int i = CMAIN; i < CIN; ++i) {
        float s0 = in_s[(r + 0)  * PIN + i];
        float s1 = in_s[(r + 8)  * PIN + i];
        float s2 = in_s[(r + 16) * PIN + i];
        float s3 = in_s[(r + 24) * PIN + i];
        const float4* wp = (const float4*)(wbase + i * COUT);
#pragma unroll
        for (int v = 0; v < JW / 4; ++v) {
            float4 w = __ldg(wp + v);
            acc[0][v * 4 + 0] = fmaf(s0, w.x, acc[0][v * 4 + 0]);
            acc[0][v * 4 + 1] = fmaf(s0, w.y, acc[0][v * 4 + 1]);
            acc[0][v * 4 + 2] = fmaf(s0, w.z, acc[0][v * 4 + 2]);
            acc[0][v * 4 + 3] = fmaf(s0, w.w, acc[0][v * 4 + 3]);
            acc[1][v * 4 + 0] = fmaf(s1, w.x, acc[1][v * 4 + 0]);
            acc[1][v * 4 + 1] = fmaf(s1, w.y, acc[1][v * 4 + 1]);
            acc[1][v * 4 + 2] = fmaf(s1, w.z, acc[1][v * 4 + 2]);
            acc[1][v * 4 + 3] = fmaf(s1, w.w, acc[1][v * 4 + 3]);
            acc[2][v * 4 + 0] = fmaf(s2, w.x, acc[2][v * 4 + 0]);
            acc[2][v * 4 + 1] = fmaf(s2, w.y, acc[2][v * 4 + 1]);
            acc[2][v * 4 + 2] = fmaf(s2, w.z, acc[2][v * 4 + 2]);
            acc[2][v * 4 + 3] = fmaf(s2, w.w, acc[2][v * 4 + 3]);
            acc[3][v * 4 + 0] = fmaf(s3, w.x, acc[3][v * 4 + 0]);
            acc[3][v * 4 + 1] = fmaf(s3, w.y, acc[3][v * 4 + 1]);
            acc[3][v * 4 + 2] = fmaf(s3, w.z, acc[3][v * 4 + 2]);
            acc[3][v * 4 + 3] = fmaf(s3, w.w, acc[3][v * 4 + 3]);
        }
    }
#pragma unroll
    for (int j = 0; j < JW; ++j) {
        float bj = __ldg(bias + c * JW + j);
#pragma unroll
        for (int m = 0; m < 4; ++m)
            out_s[(r + 8 * m) * POUT + c * JW + j] = acc[m][j] + bj;
    }
}

template <int C, int P>
__device__ __forceinline__ void ln_relu(float* buf,
                                        const float* __restrict__ g,
                                        const float* __restrict__ be, int tid) {
    const int s = tid >> 2, q = tid & 3;  // 4 threads per sample
    constexpr int SPAN = C / 4;
    float* row = buf + s * P + q * SPAN;
    float vals[SPAN];
    float sum = 0.0f;
#pragma unroll
    for (int j = 0; j < SPAN; ++j) { vals[j] = row[j]; sum += vals[j]; }
    sum += __shfl_xor_sync(0xffffffffu, sum, 1);
    sum += __shfl_xor_sync(0xffffffffu, sum, 2);
    const float mu = sum * (1.0f / C);
    float sq = 0.0f;
#pragma unroll
    for (int j = 0; j < SPAN; ++j) { float d = vals[j] - mu; sq += d * d; }
    sq += __shfl_xor_sync(0xffffffffu, sq, 1);
    sq += __shfl_xor_sync(0xffffffffu, sq, 2);
    const float inv = rsqrtf(sq * (1.0f / C) + 1e-5f);
#pragma unroll
    for (int j = 0; j < SPAN; ++j) {
        int jj = q * SPAN + j;
        float v = (vals[j] - mu) * inv * __ldg(g + jj) + __ldg(be + jj);
        row[j] = fmaxf(v, 0.0f);
    }
}

__global__ __launch_bounds__(128) void mlp_kernel(
    const float* __restrict__ xyz, const float* __restrict__ points,
    const float* __restrict__ new_xyz,
    const float* __restrict__ W1, const float* __restrict__ b1,
    const float* __restrict__ g1, const float* __restrict__ be1,
    const float* __restrict__ W2, const float* __restrict__ b2,
    const float* __restrict__ g2, const float* __restrict__ be2,
    const float* __restrict__ W3, const float* __restrict__ b3,
    const float* __restrict__ g3, const float* __restrict__ be3,
    float* __restrict__ new_points) {
    __shared__ float bufA[32 * PIN_A];
    __shared__ float bufB[32 * PIN_B];
    __shared__ int   sIdx[32];
    __shared__ float sCen[3];

    const int pair = blockIdx.x;        // b*1024 + s
    const int b    = pair >> 10;
    const int tid  = threadIdx.x;

    if (tid < 32) sIdx[tid] = g_group_idx[pair * NSAMPLE + tid];
    if (tid < 3)  sCen[tid] = new_xyz[(size_t)pair * 3 + tid];
    __syncthreads();

    // gather: 4 threads per sample; 67 channels = [xyz-offset(3), points(64)]
    {
        const int k = tid >> 2, q = tid & 3;
        const int n = sIdx[k];
        const float4* prow = (const float4*)(points + ((size_t)b * NPTS + n) * 64) + q * 4;
        float* dst = bufA + k * PIN_A + 3 + q * 16;
#pragma unroll
        for (int v = 0; v < 4; ++v) {
            float4 f = __ldg(prow + v);
            dst[v * 4 + 0] = f.x;
            dst[v * 4 + 1] = f.y;
            dst[v * 4 + 2] = f.z;
            dst[v * 4 + 3] = f.w;
        }
        if (q == 0) {
            const float* xr = xyz + ((size_t)b * NPTS + n) * 3;
            bufA[k * PIN_A + 0] = xr[0] - sCen[0];
            bufA[k * PIN_A + 1] = xr[1] - sCen[1];
            bufA[k * PIN_A + 2] = xr[2] - sCen[2];
        }
    }
    __syncthreads();

    gemm_tile<67, 64, PIN_A, PIN_B>(bufA, W1, b1, bufB, tid);
    __syncthreads();
    ln_relu<64, PIN_B>(bufB, g1, be1, tid);
    __syncthreads();

    gemm_tile<64, 64, PIN_B, PIN_A>(bufB, W2, b2, bufA, tid);
    __syncthreads();
    ln_relu<64, PIN_A>(bufA, g2, be2, tid);
    __syncthreads();

    gemm_tile<64, 128, PIN_A, PIN_B>(bufA, W3, b3, bufB, tid);
    __syncthreads();
    ln_relu<128, PIN_B>(bufB, g3, be3, tid);
    __syncthreads();

    // max over the 32 group samples; relu outputs >= 0 so init 0 is exact
    {
        const int j = tid;
        float m = 0.0f;
#pragma unroll 8
        for (int k = 0; k < 32; ++k) m = fmaxf(m, bufB[k * PIN_B + j]);
        new_points[(size_t)pair * 128 + j] = m;
    }
}

// ---------------------------------------------------------------------------
extern "C" void kernel_launch(void* const* d_in, const int* in_sizes, int n_in,
                              void* d_out, int out_size) {
    (void)in_sizes; (void)n_in; (void)out_size;
    const float* xyz    = (const float*)d_in[0];
    const float* points = (const float*)d_in[1];
    const float* W1  = (const float*)d_in[2];
    const float* b1  = (const float*)d_in[3];
    const float* g1  = (const float*)d_in[4];
    const float* be1 = (const float*)d_in[5];
    const float* W2  = (const float*)d_in[6];
    const float* b2  = (const float*)d_in[7];
    const float* g2  = (const float*)d_in[8];
    const float* be2 = (const float*)d_in[9];
    const float* W3  = (const float*)d_in[10];
    const float* b3  = (const float*)d_in[11];
    const float* g3  = (const float*)d_in[12];
    const float* be3 = (const float*)d_in[13];

    float* out        = (float*)d_out;
    float* new_xyz    = out;                          // [8,1024,3]
    float* new_points = out + BATCH * NPOINTS * 3;    // [8,1024,128]

    fps_kernel<<<BATCH, 512>>>(xyz, new_xyz);
    ball_kernel<<<dim3(NPOINTS / 8, BATCH), 256, NPTS * 3 * sizeof(float)>>>(xyz, new_xyz);
    mlp_kernel<<<BATCH * NPOINTS, 128>>>(xyz, points, new_xyz,
                                         W1, b1, g1, be1,
                                         W2, b2, g2, be2,
                                         W3, b3, g3, be3,
                                         new_points);
}

// round 8
// speedup vs baseline: 1.4889x; 1.0842x over previous
#include <cuda_runtime.h>

#define BATCH   8
#define NPTS    4096
#define NPOINTS 1024
#define NSAMPLE 32
#define PIN_A   68    // padded row, 272B (16B-aligned rows)
#define PIN_B   132   // padded row, 528B (16B-aligned rows)

// scratch (allocation-free rule: __device__ globals)
__device__ int g_group_idx[BATCH * NPOINTS * NSAMPLE];

// Non-FMA squared distance matching XLA's unfused mul/add reduce ((d0^2+d1^2)+d2^2)
__device__ __forceinline__ float sqd_nofma(float x, float y, float z,
                                           float cx, float cy, float cz) {
    float dx = x - cx, dy = y - cy, dz = z - cz;
    return __fadd_rn(__fadd_rn(__fmul_rn(dx, dx), __fmul_rn(dy, dy)), __fmul_rn(dz, dz));
}

// ---- packed f32x2 helpers (Blackwell): per-lane IEEE .rn, bit-identical to scalar ----
__device__ __forceinline__ unsigned long long f2_add(unsigned long long a, unsigned long long b) {
    unsigned long long r;
    asm("add.rn.f32x2 %0, %1, %2;" : "=l"(r) : "l"(a), "l"(b));
    return r;
}
__device__ __forceinline__ unsigned long long f2_mul(unsigned long long a, unsigned long long b) {
    unsigned long long r;
    asm("mul.rn.f32x2 %0, %1, %2;" : "=l"(r) : "l"(a), "l"(b));
    return r;
}
__device__ __forceinline__ unsigned long long f2_pack(float lo, float hi) {
    unsigned long long r;
    asm("mov.b64 %0, {%1, %2};" : "=l"(r) : "f"(lo), "f"(hi));
    return r;
}
__device__ __forceinline__ void f2_unpack(unsigned long long v, float& lo, float& hi) {
    asm("mov.b64 {%0, %1}, %2;" : "=f"(lo), "=f"(hi) : "l"(v));
}

// ---------------------------------------------------------------------------
// Kernel 1: farthest point sampling (unchanged from R7 — near structural floor).
// ---------------------------------------------------------------------------
__global__ __launch_bounds__(512) void fps_kernel(const float* __restrict__ xyz,
                                                  float* __restrict__ new_xyz) {
    const int b    = blockIdx.x;
    const int tid  = threadIdx.x;
    const int lane = tid & 31;
    const float* base = xyz + (size_t)b * NPTS * 3;

    unsigned long long pxp[4], pyp[4], pzp[4];
    float pd[8];
#pragma unroll
    for (int p = 0; p < 4; ++p) {
        int n0 = tid + p * 512;
        int n1 = n0 + 2048;
        pxp[p] = f2_pack(base[n0 * 3 + 0], base[n1 * 3 + 0]);
        pyp[p] = f2_pack(base[n0 * 3 + 1], base[n1 * 3 + 1]);
        pzp[p] = f2_pack(base[n0 * 3 + 2], base[n1 * 3 + 2]);
        pd[p] = 1e10f; pd[p + 4] = 1e10f;
    }

    __shared__ uint2 sWarp[32];   // two ping-pong banks of 16: {distbits, idx}

    float cx = __ldg(base + 0), cy = __ldg(base + 1), cz = __ldg(base + 2);
    if (tid == 0) {
        float* o = new_xyz + (size_t)b * NPOINTS * 3;
        o[0] = cx; o[1] = cy; o[2] = cz;
    }

    int bank = 0;
    for (int t = 1; t < NPOINTS; ++t) {
        const unsigned long long ncx2 = f2_pack(-cx, -cx);
        const unsigned long long ncy2 = f2_pack(-cy, -cy);
        const unsigned long long ncz2 = f2_pack(-cz, -cz);
#pragma unroll
        for (int p = 0; p < 4; ++p) {
            unsigned long long dx = f2_add(pxp[p], ncx2);
            unsigned long long dy = f2_add(pyp[p], ncy2);
            unsigned long long dz = f2_add(pzp[p], ncz2);
            unsigned long long s  = f2_add(f2_add(f2_mul(dx, dx), f2_mul(dy, dy)),
                                           f2_mul(dz, dz));
            float lo, hi;
            f2_unpack(s, lo, hi);
            pd[p]     = fminf(pd[p],     lo);
            pd[p + 4] = fminf(pd[p + 4], hi);
        }

        float m0 = fmaxf(pd[0], pd[1]);
        float m1 = fmaxf(pd[2], pd[3]);
        float m2 = fmaxf(pd[4], pd[5]);
        float m3 = fmaxf(pd[6], pd[7]);
        const float bd = fmaxf(fmaxf(m0, m1), fmaxf(m2, m3));

        int bi = 0x7fffffff;
#pragma unroll
        for (int p = 0; p < 4; ++p)
            bi = min(bi, (pd[p] == bd) ? (tid + p * 512) : 0x7fffffff);
#pragma unroll
        for (int p = 0; p < 4; ++p)
            bi = min(bi, (pd[p + 4] == bd) ? (tid + p * 512 + 2048) : 0x7fffffff);

        const unsigned bdb = __float_as_uint(bd);
        const unsigned wd  = __reduce_max_sync(0xffffffffu, bdb);
        const unsigned wi  = __reduce_min_sync(0xffffffffu,
                                (bdb == wd) ? (unsigned)bi : 0xffffffffu);
        if (lane == 0) sWarp[bank * 16 + (tid >> 5)] = make_uint2(wd, wi);
        __syncthreads();

        const uint2 k  = sWarp[bank * 16 + (lane & 15)];
        const unsigned gd = __reduce_max_sync(0xffffffffu, k.x);
        const unsigned gi = __reduce_min_sync(0xffffffffu,
                                (k.x == gd) ? k.y : 0xffffffffu);
        const int idx = (int)gi;
        cx = __ldg(base + idx * 3 + 0);
        cy = __ldg(base + idx * 3 + 1);
        cz = __ldg(base + idx * 3 + 2);
        if (tid == 0) {
            float* o = new_xyz + ((size_t)b * NPOINTS + t) * 3;
            o[0] = cx; o[1] = cy; o[2] = cz;
        }
        bank ^= 1;
    }
}

// ---------------------------------------------------------------------------
// Kernel 2: ball query (unchanged).
// ---------------------------------------------------------------------------
__global__ __launch_bounds__(256) void ball_kernel(const float* __restrict__ xyz,
                                                   const float* __restrict__ new_xyz) {
    extern __shared__ float sxyz[];  // 48 KB
    const int b = blockIdx.y;
    const float* base = xyz + (size_t)b * NPTS * 3;
    for (int i = threadIdx.x; i < NPTS * 3 / 4; i += 256)
        ((float4*)sxyz)[i] = ((const float4*)base)[i];
    __syncthreads();

    const int warp = threadIdx.x >> 5;
    const int lane = threadIdx.x & 31;
    const int s    = blockIdx.x * 8 + warp;

    const float* c = new_xyz + ((size_t)b * NPOINTS + s) * 3;
    const float cx = c[0], cy = c[1], cz = c[2];
    const float R2 = (float)(0.2 * 0.2);

    int* out  = g_group_idx + ((size_t)(b * NPOINTS + s)) * NSAMPLE;
    int cnt = 0, first = -1;
    for (int r = 0; r < NPTS / 32; ++r) {
        int n = r * 32 + lane;
        float d = sqd_nofma(sxyz[n * 3], sxyz[n * 3 + 1], sxyz[n * 3 + 2], cx, cy, cz);
        bool ok = !(d > R2);
        unsigned m = __ballot_sync(0xffffffffu, ok);
        if (first < 0 && m) first = r * 32 + (__ffs(m) - 1);
        if (ok) {
            int pos = cnt + __popc(m & ((1u << lane) - 1u));
            if (pos < NSAMPLE) out[pos] = n;
        }
        cnt += __popc(m);
        if (cnt >= NSAMPLE) break;
    }
    if (cnt < NSAMPLE && lane >= cnt && lane < NSAMPLE) out[lane] = first;
}

// ---------------------------------------------------------------------------
// Kernel 3: MLP v2 — warp-row mapping (c = tid&15, r = tid>>4) so each
// half-warp owns a full LN row. LN runs on register accumulators via 4
// butterfly shuffles; bias folded into acc init; LN+ReLU+STS.128 fused in the
// GEMM epilogue. 5 block barriers (was 7), no LN smem round trips.
// ---------------------------------------------------------------------------
template <int CIN, int COUT, int PIN>
__device__ __forceinline__ void gemm_acc(const float* in_s,
                                         const float* __restrict__ W,
                                         const float* __restrict__ bias,
                                         float acc[4][COUT / 16],
                                         int c, int r) {
    constexpr int JW = COUT / 16;
#pragma unroll
    for (int j = 0; j < JW; ++j) {
        float bj = __ldg(bias + c * JW + j);
#pragma unroll
        for (int m = 0; m < 4; ++m) acc[m][j] = bj;   // bias-first accumulation
    }

    const float* wbase = W + c * JW;
    constexpr int CMAIN = CIN & ~3;

    for (int i = 0; i < CMAIN; i += 4) {
        float4 a0 = *(const float4*)(in_s + (r + 0)  * PIN + i);
        float4 a1 = *(const float4*)(in_s + (r + 8)  * PIN + i);
        float4 a2 = *(const float4*)(in_s + (r + 16) * PIN + i);
        float4 a3 = *(const float4*)(in_s + (r + 24) * PIN + i);
        const float av[4][4] = {
            {a0.x, a1.x, a2.x, a3.x},
            {a0.y, a1.y, a2.y, a3.y},
            {a0.z, a1.z, a2.z, a3.z},
            {a0.w, a1.w, a2.w, a3.w}};
#pragma unroll
        for (int u = 0; u < 4; ++u) {
            const float4* wp = (const float4*)(wbase + (i + u) * COUT);
#pragma unroll
            for (int v = 0; v < JW / 4; ++v) {
                float4 w = __ldg(wp + v);
#pragma unroll
                for (int m = 0; m < 4; ++m) {
                    acc[m][v * 4 + 0] = fmaf(av[u][m], w.x, acc[m][v * 4 + 0]);
                    acc[m][v * 4 + 1] = fmaf(av[u][m], w.y, acc[m][v * 4 + 1]);
                    acc[m][v * 4 + 2] = fmaf(av[u][m], w.z, acc[m][v * 4 + 2]);
                    acc[m][v * 4 + 3] = fmaf(av[u][m], w.w, acc[m][v * 4 + 3]);
                }
            }
        }
    }
    for (int i = CMAIN; i < CIN; ++i) {    // remainder (layer 1: 64..66)
        float s0 = in_s[(r + 0)  * PIN + i];
        float s1 = in_s[(r + 8)  * PIN + i];
        float s2 = in_s[(r + 16) * PIN + i];
        float s3 = in_s[(r + 24) * PIN + i];
        const float4* wp = (const float4*)(wbase + i * COUT);
#pragma unroll
        for (int v = 0; v < JW / 4; ++v) {
            float4 w = __ldg(wp + v);
#pragma unroll
            for (int q = 0; q < 4; ++q) {
                acc[0][v * 4 + q] = fmaf(s0, ((const float*)&w)[q], acc[0][v * 4 + q]);
                acc[1][v * 4 + q] = fmaf(s1, ((const float*)&w)[q], acc[1][v * 4 + q]);
                acc[2][v * 4 + q] = fmaf(s2, ((const float*)&w)[q], acc[2][v * 4 + q]);
                acc[3][v * 4 + q] = fmaf(s3, ((const float*)&w)[q], acc[3][v * 4 + q]);
            }
        }
    }
}

// Register-resident LN + ReLU across the 16-lane half-warp (full warp mask;
// xor offsets <= 8 stay inside each 16-lane group). Writes result into acc.
template <int COUT>
__device__ __forceinline__ void ln_relu_reg(float acc[4][COUT / 16],
                                            const float* __restrict__ g,
                                            const float* __restrict__ be, int c) {
    constexpr int JW = COUT / 16;
    float gv[JW], bv[JW];
#pragma unroll
    for (int j = 0; j < JW; ++j) { gv[j] = __ldg(g + c * JW + j); bv[j] = __ldg(be + c * JW + j); }
#pragma unroll
    for (int m = 0; m < 4; ++m) {
        float sum = 0.0f;
#pragma unroll
        for (int j = 0; j < JW; ++j) sum += acc[m][j];
        sum += __shfl_xor_sync(0xffffffffu, sum, 1);
        sum += __shfl_xor_sync(0xffffffffu, sum, 2);
        sum += __shfl_xor_sync(0xffffffffu, sum, 4);
        sum += __shfl_xor_sync(0xffffffffu, sum, 8);
        const float mu = sum * (1.0f / COUT);
        float sq = 0.0f;
#pragma unroll
        for (int j = 0; j < JW; ++j) { float d = acc[m][j] - mu; sq += d * d; }
        sq += __shfl_xor_sync(0xffffffffu, sq, 1);
        sq += __shfl_xor_sync(0xffffffffu, sq, 2);
        sq += __shfl_xor_sync(0xffffffffu, sq, 4);
        sq += __shfl_xor_sync(0xffffffffu, sq, 8);
        const float inv = rsqrtf(sq * (1.0f / COUT) + 1e-5f);
#pragma unroll
        for (int j = 0; j < JW; ++j)
            acc[m][j] = fmaxf((acc[m][j] - mu) * inv * gv[j] + bv[j], 0.0f);
    }
}

template <int COUT, int POUT>
__device__ __forceinline__ void store_rows(const float acc[4][COUT / 16],
                                           float* out_s, int c, int r) {
    constexpr int JW = COUT / 16;
#pragma unroll
    for (int m = 0; m < 4; ++m)
#pragma unroll
        for (int v = 0; v < JW / 4; ++v)
            *(float4*)(out_s + (r + 8 * m) * POUT + c * JW + v * 4) =
                make_float4(acc[m][v * 4 + 0], acc[m][v * 4 + 1],
                            acc[m][v * 4 + 2], acc[m][v * 4 + 3]);
}

__global__ __launch_bounds__(128) void mlp_kernel(
    const float* __restrict__ xyz, const float* __restrict__ points,
    const float* __restrict__ new_xyz,
    const float* __restrict__ W1, const float* __restrict__ b1,
    const float* __restrict__ g1, const float* __restrict__ be1,
    const float* __restrict__ W2, const float* __restrict__ b2,
    const float* __restrict__ g2, const float* __restrict__ be2,
    const float* __restrict__ W3, const float* __restrict__ b3,
    const float* __restrict__ g3, const float* __restrict__ be3,
    float* __restrict__ new_points) {
    __shared__ float bufA[32 * PIN_A];
    __shared__ float bufB[32 * PIN_B];   // also holds 8x132 partial max at the end
    __shared__ int   sIdx[32];
    __shared__ float sCen[3];

    const int pair = blockIdx.x;        // b*1024 + s
    const int b    = pair >> 10;
    const int tid  = threadIdx.x;
    const int c    = tid & 15;
    const int r    = tid >> 4;

    if (tid < 32) sIdx[tid] = g_group_idx[pair * NSAMPLE + tid];
    if (tid < 3)  sCen[tid] = new_xyz[(size_t)pair * 3 + tid];
    __syncthreads();

    // gather: 4 threads per sample; 67 channels = [xyz-offset(3), points(64)]
    {
        const int k = tid >> 2, q = tid & 3;
        const int n = sIdx[k];
        const float4* prow = (const float4*)(points + ((size_t)b * NPTS + n) * 64) + q * 4;
        float* dst = bufA + k * PIN_A + 3 + q * 16;
#pragma unroll
        for (int v = 0; v < 4; ++v) {
            float4 f = __ldg(prow + v);
            dst[v * 4 + 0] = f.x;
            dst[v * 4 + 1] = f.y;
            dst[v * 4 + 2] = f.z;
            dst[v * 4 + 3] = f.w;
        }
        if (q == 0) {
            const float* xr = xyz + ((size_t)b * NPTS + n) * 3;
            bufA[k * PIN_A + 0] = xr[0] - sCen[0];
            bufA[k * PIN_A + 1] = xr[1] - sCen[1];
            bufA[k * PIN_A + 2] = xr[2] - sCen[2];
        }
    }
    __syncthreads();

    {   // layer 1: 67 -> 64
        float acc[4][4];
        gemm_acc<67, 64, PIN_A>(bufA, W1, b1, acc, c, r);
        ln_relu_reg<64>(acc, g1, be1, c);
        store_rows<64, PIN_B>(acc, bufB, c, r);
    }
    __syncthreads();

    {   // layer 2: 64 -> 64
        float acc[4][4];
        gemm_acc<64, 64, PIN_B>(bufB, W2, b2, acc, c, r);
        ln_relu_reg<64>(acc, g2, be2, c);
        store_rows<64, PIN_A>(acc, bufA, c, r);
    }
    __syncthreads();

    {   // layer 3: 64 -> 128, fused partial max over this thread's 4 samples
        float acc[4][8];
        gemm_acc<64, 128, PIN_A>(bufA, W3, b3, acc, c, r);
        ln_relu_reg<128>(acc, g3, be3, c);
#pragma unroll
        for (int j = 0; j < 8; ++j) {
            float pm = fmaxf(fmaxf(acc[0][j], acc[1][j]), fmaxf(acc[2][j], acc[3][j]));
            bufB[r * PIN_B + c * 8 + j] = pm;   // 8 x 128 partials
        }
    }
    __syncthreads();

    // final max over the 8 r-partials; relu outputs >= 0 so init 0 is exact
    {
        const int j = tid;
        float m = 0.0f;
#pragma unroll
        for (int k = 0; k < 8; ++k) m = fmaxf(m, bufB[k * PIN_B + j]);
        new_points[(size_t)pair * 128 + j] = m;
    }
}

// ---------------------------------------------------------------------------
extern "C" void kernel_launch(void* const* d_in, const int* in_sizes, int n_in,
                              void* d_out, int out_size) {
    (void)in_sizes; (void)n_in; (void)out_size;
    const float* xyz    = (const float*)d_in[0];
    const float* points = (const float*)d_in[1];
    const float* W1  = (const float*)d_in[2];
    const float* b1  = (const float*)d_in[3];
    const float* g1  = (const float*)d_in[4];
    const float* be1 = (const float*)d_in[5];
    const float* W2  = (const float*)d_in[6];
    const float* b2  = (const float*)d_in[7];
    const float* g2  = (const float*)d_in[8];
    const float* be2 = (const float*)d_in[9];
    const float* W3  = (const float*)d_in[10];
    const float* b3  = (const float*)d_in[11];
    const float* g3  = (const float*)d_in[12];
    const float* be3 = (const float*)d_in[13];

    float* out        = (float*)d_out;
    float* new_xyz    = out;                          // [8,1024,3]
    float* new_points = out + BATCH * NPOINTS * 3;    // [8,1024,128]

    fps_kernel<<<BATCH, 512>>>(xyz, new_xyz);
    ball_kernel<<<dim3(NPOINTS / 8, BATCH), 256, NPTS * 3 * sizeof(float)>>>(xyz, new_xyz);
    mlp_kernel<<<BATCH * NPOINTS, 128>>>(xyz, points, new_xyz,
                                         W1, b1, g1, be1,
                                         W2, b2, g2, be2,
                                         W3, b3, g3, be3,
                                         new_points);
}

// round 9
// speedup vs baseline: 1.6150x; 1.0847x over previous
#include <cuda_runtime.h>

#define BATCH   8
#define NPTS    4096
#define NPOINTS 1024
#define NSAMPLE 32
#define PIN_A   68
#define PIN_B   132
#define NW_PER_B 15                    // worker blocks per batch
#define NWORKERS (NW_PER_B * BATCH)    // 120
#define NBLOCKS  (BATCH + NWORKERS)    // 128 <= 148 SMs -> all resident wave 1

#define SXYZ_F   (NPTS * 3)                    // 12288 floats
#define GRP_F    (32 * PIN_A + 32 * PIN_B)     // 6400 floats per group
#define SMEM_DYN ((SXYZ_F + 4 * GRP_F) * 4 + 128 * 4 + 16 * 4)  // 152128 B

// progress[b] = number of centroids of batch b published in new_xyz
__device__ int g_progress[BATCH];

// ---------------------------------------------------------------------------
__device__ __forceinline__ float sqd_nofma(float x, float y, float z,
                                           float cx, float cy, float cz) {
    float dx = x - cx, dy = y - cy, dz = z - cz;
    return __fadd_rn(__fadd_rn(__fmul_rn(dx, dx), __fmul_rn(dy, dy)), __fmul_rn(dz, dz));
}

__device__ __forceinline__ unsigned long long f2_add(unsigned long long a, unsigned long long b) {
    unsigned long long r;
    asm("add.rn.f32x2 %0, %1, %2;" : "=l"(r) : "l"(a), "l"(b));
    return r;
}
__device__ __forceinline__ unsigned long long f2_mul(unsigned long long a, unsigned long long b) {
    unsigned long long r;
    asm("mul.rn.f32x2 %0, %1, %2;" : "=l"(r) : "l"(a), "l"(b));
    return r;
}
__device__ __forceinline__ unsigned long long f2_pack(float lo, float hi) {
    unsigned long long r;
    asm("mov.b64 %0, {%1, %2};" : "=l"(r) : "f"(lo), "f"(hi));
    return r;
}
__device__ __forceinline__ void f2_unpack(unsigned long long v, float& lo, float& hi) {
    asm("mov.b64 {%0, %1}, %2;" : "=f"(lo), "=f"(hi) : "l"(v));
}

__device__ __forceinline__ int ld_acquire(const int* p) {
    int v;
    asm volatile("ld.acquire.gpu.global.s32 %0, [%1];" : "=r"(v) : "l"(p) : "memory");
    return v;
}
__device__ __forceinline__ void st_release(int* p, int v) {
    asm volatile("st.release.gpu.global.s32 [%0], %1;" :: "l"(p), "r"(v) : "memory");
}

// ---------------------------------------------------------------------------
__global__ void reset_kernel() {
    if (threadIdx.x < BATCH) g_progress[threadIdx.x] = 0;
}

// ---------------------------------------------------------------------------
// FPS role (blocks 0..7): identical math to R7/R8 FPS, plus release-publish
// of progress after each centroid write.
// ---------------------------------------------------------------------------
__device__ void fps_role(const float* __restrict__ xyz, float* __restrict__ new_xyz,
                         int b, int tid) {
    const int lane = tid & 31;
    const float* base = xyz + (size_t)b * NPTS * 3;

    unsigned long long pxp[4], pyp[4], pzp[4];
    float pd[8];
#pragma unroll
    for (int p = 0; p < 4; ++p) {
        int n0 = tid + p * 512;
        int n1 = n0 + 2048;
        pxp[p] = f2_pack(base[n0 * 3 + 0], base[n1 * 3 + 0]);
        pyp[p] = f2_pack(base[n0 * 3 + 1], base[n1 * 3 + 1]);
        pzp[p] = f2_pack(base[n0 * 3 + 2], base[n1 * 3 + 2]);
        pd[p] = 1e10f; pd[p + 4] = 1e10f;
    }

    __shared__ uint2 sWarp[32];   // ping-pong banks of 16

    float cx = __ldg(base + 0), cy = __ldg(base + 1), cz = __ldg(base + 2);
    if (tid == 0) {
        float* o = new_xyz + (size_t)b * NPOINTS * 3;
        o[0] = cx; o[1] = cy; o[2] = cz;
        st_release(&g_progress[b], 1);
    }

    int bank = 0;
    for (int t = 1; t < NPOINTS; ++t) {
        const unsigned long long ncx2 = f2_pack(-cx, -cx);
        const unsigned long long ncy2 = f2_pack(-cy, -cy);
        const unsigned long long ncz2 = f2_pack(-cz, -cz);
#pragma unroll
        for (int p = 0; p < 4; ++p) {
            unsigned long long dx = f2_add(pxp[p], ncx2);
            unsigned long long dy = f2_add(pyp[p], ncy2);
            unsigned long long dz = f2_add(pzp[p], ncz2);
            unsigned long long s  = f2_add(f2_add(f2_mul(dx, dx), f2_mul(dy, dy)),
                                           f2_mul(dz, dz));
            float lo, hi;
            f2_unpack(s, lo, hi);
            pd[p]     = fminf(pd[p],     lo);
            pd[p + 4] = fminf(pd[p + 4], hi);
        }

        float m0 = fmaxf(pd[0], pd[1]);
        float m1 = fmaxf(pd[2], pd[3]);
        float m2 = fmaxf(pd[4], pd[5]);
        float m3 = fmaxf(pd[6], pd[7]);
        const float bd = fmaxf(fmaxf(m0, m1), fmaxf(m2, m3));

        int bi = 0x7fffffff;
#pragma unroll
        for (int p = 0; p < 4; ++p)
            bi = min(bi, (pd[p] == bd) ? (tid + p * 512) : 0x7fffffff);
#pragma unroll
        for (int p = 0; p < 4; ++p)
            bi = min(bi, (pd[p + 4] == bd) ? (tid + p * 512 + 2048) : 0x7fffffff);

        const unsigned bdb = __float_as_uint(bd);
        const unsigned wd  = __reduce_max_sync(0xffffffffu, bdb);
        const unsigned wi  = __reduce_min_sync(0xffffffffu,
                                (bdb == wd) ? (unsigned)bi : 0xffffffffu);
        if (lane == 0) sWarp[bank * 16 + (tid >> 5)] = make_uint2(wd, wi);
        __syncthreads();

        const uint2 k  = sWarp[bank * 16 + (lane & 15)];
        const unsigned gd = __reduce_max_sync(0xffffffffu, k.x);
        const unsigned gi = __reduce_min_sync(0xffffffffu,
                                (k.x == gd) ? k.y : 0xffffffffu);
        const int idx = (int)gi;
        cx = __ldg(base + idx * 3 + 0);
        cy = __ldg(base + idx * 3 + 1);
        cz = __ldg(base + idx * 3 + 2);
        if (tid == 0) {
            float* o = new_xyz + ((size_t)b * NPOINTS + t) * 3;
            o[0] = cx; o[1] = cy; o[2] = cz;
            st_release(&g_progress[b], t + 1);
        }
        bank ^= 1;
    }
}

// ---------------------------------------------------------------------------
// MLP building blocks (identical arithmetic to R8)
// ---------------------------------------------------------------------------
template <int CIN, int COUT, int PIN>
__device__ __forceinline__ void gemm_acc(const float* in_s,
                                         const float* __restrict__ W,
                                         const float* __restrict__ bias,
                                         float acc[4][COUT / 16],
                                         int c, int r) {
    constexpr int JW = COUT / 16;
#pragma unroll
    for (int j = 0; j < JW; ++j) {
        float bj = __ldg(bias + c * JW + j);
#pragma unroll
        for (int m = 0; m < 4; ++m) acc[m][j] = bj;
    }

    const float* wbase = W + c * JW;
    constexpr int CMAIN = CIN & ~3;

    for (int i = 0; i < CMAIN; i += 4) {
        float4 a0 = *(const float4*)(in_s + (r + 0)  * PIN + i);
        float4 a1 = *(const float4*)(in_s + (r + 8)  * PIN + i);
        float4 a2 = *(const float4*)(in_s + (r + 16) * PIN + i);
        float4 a3 = *(const float4*)(in_s + (r + 24) * PIN + i);
        const float av[4][4] = {
            {a0.x, a1.x, a2.x, a3.x},
            {a0.y, a1.y, a2.y, a3.y},
            {a0.z, a1.z, a2.z, a3.z},
            {a0.w, a1.w, a2.w, a3.w}};
#pragma unroll
        for (int u = 0; u < 4; ++u) {
            const float4* wp = (const float4*)(wbase + (i + u) * COUT);
#pragma unroll
            for (int v = 0; v < JW / 4; ++v) {
                float4 w = __ldg(wp + v);
#pragma unroll
                for (int m = 0; m < 4; ++m) {
                    acc[m][v * 4 + 0] = fmaf(av[u][m], w.x, acc[m][v * 4 + 0]);
                    acc[m][v * 4 + 1] = fmaf(av[u][m], w.y, acc[m][v * 4 + 1]);
                    acc[m][v * 4 + 2] = fmaf(av[u][m], w.z, acc[m][v * 4 + 2]);
                    acc[m][v * 4 + 3] = fmaf(av[u][m], w.w, acc[m][v * 4 + 3]);
                }
            }
        }
    }
    for (int i = CMAIN; i < CIN; ++i) {
        float s0 = in_s[(r + 0)  * PIN + i];
        float s1 = in_s[(r + 8)  * PIN + i];
        float s2 = in_s[(r + 16) * PIN + i];
        float s3 = in_s[(r + 24) * PIN + i];
        const float4* wp = (const float4*)(wbase + i * COUT);
#pragma unroll
        for (int v = 0; v < JW / 4; ++v) {
            float4 w = __ldg(wp + v);
#pragma unroll
            for (int q = 0; q < 4; ++q) {
                acc[0][v * 4 + q] = fmaf(s0, ((const float*)&w)[q], acc[0][v * 4 + q]);
                acc[1][v * 4 + q] = fmaf(s1, ((const float*)&w)[q], acc[1][v * 4 + q]);
                acc[2][v * 4 + q] = fmaf(s2, ((const float*)&w)[q], acc[2][v * 4 + q]);
                acc[3][v * 4 + q] = fmaf(s3, ((const float*)&w)[q], acc[3][v * 4 + q]);
            }
        }
    }
}

template <int COUT>
__device__ __forceinline__ void ln_relu_reg(float acc[4][COUT / 16],
                                            const float* __restrict__ g,
                                            const float* __restrict__ be, int c) {
    constexpr int JW = COUT / 16;
    float gv[JW], bv[JW];
#pragma unroll
    for (int j = 0; j < JW; ++j) { gv[j] = __ldg(g + c * JW + j); bv[j] = __ldg(be + c * JW + j); }
#pragma unroll
    for (int m = 0; m < 4; ++m) {
        float sum = 0.0f;
#pragma unroll
        for (int j = 0; j < JW; ++j) sum += acc[m][j];
        sum += __shfl_xor_sync(0xffffffffu, sum, 1);
        sum += __shfl_xor_sync(0xffffffffu, sum, 2);
        sum += __shfl_xor_sync(0xffffffffu, sum, 4);
        sum += __shfl_xor_sync(0xffffffffu, sum, 8);
        const float mu = sum * (1.0f / COUT);
        float sq = 0.0f;
#pragma unroll
        for (int j = 0; j < JW; ++j) { float d = acc[m][j] - mu; sq += d * d; }
        sq += __shfl_xor_sync(0xffffffffu, sq, 1);
        sq += __shfl_xor_sync(0xffffffffu, sq, 2);
        sq += __shfl_xor_sync(0xffffffffu, sq, 4);
        sq += __shfl_xor_sync(0xffffffffu, sq, 8);
        const float inv = rsqrtf(sq * (1.0f / COUT) + 1e-5f);
#pragma unroll
        for (int j = 0; j < JW; ++j)
            acc[m][j] = fmaxf((acc[m][j] - mu) * inv * gv[j] + bv[j], 0.0f);
    }
}

template <int COUT, int POUT>
__device__ __forceinline__ void store_rows(const float acc[4][COUT / 16],
                                           float* out_s, int c, int r) {
    constexpr int JW = COUT / 16;
#pragma unroll
    for (int m = 0; m < 4; ++m)
#pragma unroll
        for (int v = 0; v < JW / 4; ++v)
            *(float4*)(out_s + (r + 8 * m) * POUT + c * JW + v * 4) =
                make_float4(acc[m][v * 4 + 0], acc[m][v * 4 + 1],
                            acc[m][v * 4 + 2], acc[m][v * 4 + 3]);
}

// ---------------------------------------------------------------------------
// Worker role (blocks 8..127): 4 groups of 128 threads; each group runs the
// full ball->gather->MLP->max pipeline for one s, paced by g_progress[b].
// ---------------------------------------------------------------------------
__device__ void worker_role(const float* __restrict__ xyz,
                            const float* __restrict__ points,
                            const float* __restrict__ new_xyz,
                            const float* __restrict__ W1, const float* __restrict__ b1,
                            const float* __restrict__ g1, const float* __restrict__ be1,
                            const float* __restrict__ W2, const float* __restrict__ b2,
                            const float* __restrict__ g2, const float* __restrict__ be2,
                            const float* __restrict__ W3, const float* __restrict__ b3,
                            const float* __restrict__ g3, const float* __restrict__ be3,
                            float* __restrict__ new_points,
                            float* smem, int wb, int tid) {
    const int b = wb & 7;          // batch
    const int w = wb >> 3;         // 0..14 worker index within batch
    const int grp  = tid >> 7;     // 0..3
    const int gtid = tid & 127;
    const int c = gtid & 15;
    const int r = gtid >> 4;

    float* sxyz = smem;                         // 12288 floats
    float* gbase = smem + SXYZ_F + grp * GRP_F;
    float* bufA  = gbase;                       // 32*68
    float* bufB  = gbase + 32 * PIN_A;          // 32*132
    int*   sIdx  = (int*)(smem + SXYZ_F + 4 * GRP_F);   // 128 ints (32 per group)
    float* sCen  = (float*)(sIdx + 128);                 // 16 floats (4 per group)

    // stage batch xyz into smem (immutable input)
    {
        const float4* src = (const float4*)(xyz + (size_t)b * NPTS * 3);
        for (int i = tid; i < SXYZ_F / 4; i += 512)
            ((float4*)sxyz)[i] = src[i];
    }
    __syncthreads();

    for (int base = w * 4; base < NPOINTS; base += NW_PER_B * 4) {
        const int s = base + grp;
        // ---- pace on producer ----
        if (tid == 0) {
            const int need = min(base + 4, NPOINTS);
            while (ld_acquire(&g_progress[b]) < need) { }
        }
        __syncthreads();

        // ---- ball query: warp 0 of each group ----
        if (gtid < 32) {
            const int lane = gtid;
            const float* cp = new_xyz + ((size_t)b * NPOINTS + s) * 3;
            const float cx = __ldcg(cp + 0);   // L2-only: line may be stale in L1
            const float cy = __ldcg(cp + 1);
            const float cz = __ldcg(cp + 2);
            if (lane < 3) sCen[grp * 4 + lane] = __ldcg(cp + lane);
            const float R2 = (float)(0.2 * 0.2);
            int* out = sIdx + grp * 32;
            int cnt = 0, first = -1;
            for (int rr = 0; rr < NPTS / 32; ++rr) {
                int n = rr * 32 + lane;
                float d = sqd_nofma(sxyz[n * 3], sxyz[n * 3 + 1], sxyz[n * 3 + 2],
                                    cx, cy, cz);
                bool ok = !(d > R2);
                unsigned m = __ballot_sync(0xffffffffu, ok);
                if (first < 0 && m) first = rr * 32 + (__ffs(m) - 1);
                if (ok) {
                    int pos = cnt + __popc(m & ((1u << lane) - 1u));
                    if (pos < NSAMPLE) out[pos] = n;
                }
                cnt += __popc(m);
                if (cnt >= NSAMPLE) break;
            }
            if (cnt < NSAMPLE && lane >= cnt && lane < NSAMPLE) out[lane] = first;
        }
        __syncthreads();

        // ---- gather: 4 threads per sample ----
        {
            const int k = gtid >> 2, q = gtid & 3;
            const int n = sIdx[grp * 32 + k];
            const float4* prow = (const float4*)(points + ((size_t)b * NPTS + n) * 64) + q * 4;
            float* dst = bufA + k * PIN_A + 3 + q * 16;
#pragma unroll
            for (int v = 0; v < 4; ++v) {
                float4 f = __ldg(prow + v);
                dst[v * 4 + 0] = f.x;
                dst[v * 4 + 1] = f.y;
                dst[v * 4 + 2] = f.z;
                dst[v * 4 + 3] = f.w;
            }
            if (q == 0) {
                bufA[k * PIN_A + 0] = sxyz[n * 3 + 0] - sCen[grp * 4 + 0];
                bufA[k * PIN_A + 1] = sxyz[n * 3 + 1] - sCen[grp * 4 + 1];
                bufA[k * PIN_A + 2] = sxyz[n * 3 + 2] - sCen[grp * 4 + 2];
            }
        }
        __syncthreads();

        {   // layer 1: 67 -> 64
            float acc[4][4];
            gemm_acc<67, 64, PIN_A>(bufA, W1, b1, acc, c, r);
            ln_relu_reg<64>(acc, g1, be1, c);
            store_rows<64, PIN_B>(acc, bufB, c, r);
        }
        __syncthreads();

        {   // layer 2: 64 -> 64
            float acc[4][4];
            gemm_acc<64, 64, PIN_B>(bufB, W2, b2, acc, c, r);
            ln_relu_reg<64>(acc, g2, be2, c);
            store_rows<64, PIN_A>(acc, bufA, c, r);
        }
        __syncthreads();

        {   // layer 3: 64 -> 128, fused partial max over 4 samples
            float acc[4][8];
            gemm_acc<64, 128, PIN_A>(bufA, W3, b3, acc, c, r);
            ln_relu_reg<128>(acc, g3, be3, c);
#pragma unroll
            for (int j = 0; j < 8; ++j) {
                float pm = fmaxf(fmaxf(acc[0][j], acc[1][j]), fmaxf(acc[2][j], acc[3][j]));
                bufB[r * PIN_B + c * 8 + j] = pm;
            }
        }
        __syncthreads();

        {   // final max over 8 r-partials; relu >= 0 so init 0 exact
            float m = 0.0f;
#pragma unroll
            for (int k = 0; k < 8; ++k) m = fmaxf(m, bufB[k * PIN_B + gtid]);
            new_points[((size_t)b * NPOINTS + s) * 128 + gtid] = m;
        }
        __syncthreads();   // protect bufs before next iteration's gather
    }
}

// ---------------------------------------------------------------------------
__global__ __launch_bounds__(512, 1) void fused_kernel(
    const float* __restrict__ xyz, const float* __restrict__ points,
    const float* __restrict__ W1, const float* __restrict__ b1,
    const float* __restrict__ g1, const float* __restrict__ be1,
    const float* __restrict__ W2, const float* __restrict__ b2,
    const float* __restrict__ g2, const float* __restrict__ be2,
    const float* __restrict__ W3, const float* __restrict__ b3,
    const float* __restrict__ g3, const float* __restrict__ be3,
    float* __restrict__ new_xyz, float* __restrict__ new_points) {
    extern __shared__ float smem[];
    const int tid = threadIdx.x;
    if (blockIdx.x < BATCH) {
        fps_role(xyz, new_xyz, blockIdx.x, tid);
    } else {
        worker_role(xyz, points, new_xyz,
                    W1, b1, g1, be1, W2, b2, g2, be2, W3, b3, g3, be3,
                    new_points, smem, blockIdx.x - BATCH, tid);
    }
}

// ---------------------------------------------------------------------------
extern "C" void kernel_launch(void* const* d_in, const int* in_sizes, int n_in,
                              void* d_out, int out_size) {
    (void)in_sizes; (void)n_in; (void)out_size;
    const float* xyz    = (const float*)d_in[0];
    const float* points = (const float*)d_in[1];
    const float* W1  = (const float*)d_in[2];
    const float* b1  = (const float*)d_in[3];
    const float* g1  = (const float*)d_in[4];
    const float* be1 = (const float*)d_in[5];
    const float* W2  = (const float*)d_in[6];
    const float* b2  = (const float*)d_in[7];
    const float* g2  = (const float*)d_in[8];
    const float* be2 = (const float*)d_in[9];
    const float* W3  = (const float*)d_in[10];
    const float* b3  = (const float*)d_in[11];
    const float* g3  = (const float*)d_in[12];
    const float* be3 = (const float*)d_in[13];

    float* out        = (float*)d_out;
    float* new_xyz    = out;                          // [8,1024,3]
    float* new_points = out + BATCH * NPOINTS * 3;    // [8,1024,128]

    static int smem_set = 0;
    cudaFuncSetAttribute(fused_kernel, cudaFuncAttributeMaxDynamicSharedMemorySize,
                         SMEM_DYN);
    (void)smem_set;

    reset_kernel<<<1, 32>>>();
    fused_kernel<<<NBLOCKS, 512, SMEM_DYN>>>(xyz, points,
                                             W1, b1, g1, be1,
                                             W2, b2, g2, be2,
                                             W3, b3, g3, be3,
                                             new_xyz, new_points);
}

// round 10
// speedup vs baseline: 1.8299x; 1.1330x over previous
#include <cuda_runtime.h>

#define BATCH   8
#define NPTS    4096
#define NPOINTS 1024
#define NSAMPLE 32
#define PIN_A   68
#define PIN_B   132
#define NW_PER_B 17                    // worker blocks per batch
#define NWORKERS (NW_PER_B * BATCH)    // 136
#define NBLOCKS  (BATCH + NWORKERS)    // 144 <= 148 SMs -> all resident wave 1

#define SXYZ_F   (NPTS * 3)                    // 12288 floats
#define GRP_F    (32 * PIN_A + 32 * PIN_B)     // 6400 floats per group
#define SMEM_DYN ((SXYZ_F + 4 * GRP_F) * 4 + 128 * 4 + 16 * 4)  // 152128 B

// progress[b*32] = number of centroids of batch b published (128B line per batch)
__device__ int g_progress[BATCH * 32];

// ---------------------------------------------------------------------------
__device__ __forceinline__ float sqd_nofma(float x, float y, float z,
                                           float cx, float cy, float cz) {
    float dx = x - cx, dy = y - cy, dz = z - cz;
    return __fadd_rn(__fadd_rn(__fmul_rn(dx, dx), __fmul_rn(dy, dy)), __fmul_rn(dz, dz));
}

__device__ __forceinline__ unsigned long long f2_add(unsigned long long a, unsigned long long b) {
    unsigned long long r;
    asm("add.rn.f32x2 %0, %1, %2;" : "=l"(r) : "l"(a), "l"(b));
    return r;
}
__device__ __forceinline__ unsigned long long f2_mul(unsigned long long a, unsigned long long b) {
    unsigned long long r;
    asm("mul.rn.f32x2 %0, %1, %2;" : "=l"(r) : "l"(a), "l"(b));
    return r;
}
__device__ __forceinline__ unsigned long long f2_pack(float lo, float hi) {
    unsigned long long r;
    asm("mov.b64 %0, {%1, %2};" : "=l"(r) : "f"(lo), "f"(hi));
    return r;
}
__device__ __forceinline__ void f2_unpack(unsigned long long v, float& lo, float& hi) {
    asm("mov.b64 {%0, %1}, %2;" : "=f"(lo), "=f"(hi) : "l"(v));
}

__device__ __forceinline__ int ld_acquire(const int* p) {
    int v;
    asm volatile("ld.acquire.gpu.global.s32 %0, [%1];" : "=r"(v) : "l"(p) : "memory");
    return v;
}
__device__ __forceinline__ void st_release(int* p, int v) {
    asm volatile("st.release.gpu.global.s32 [%0], %1;" :: "l"(p), "r"(v) : "memory");
}

// ---------------------------------------------------------------------------
__global__ void reset_kernel() {
    if (threadIdx.x < BATCH * 32) g_progress[threadIdx.x] = 0;
}

// ---------------------------------------------------------------------------
// FPS role (blocks 0..7): identical selection math; progress published every
// 4 steps (workers consume 4-centroid tiles) to keep the release fence off
// the per-step critical path.
// ---------------------------------------------------------------------------
__device__ void fps_role(const float* __restrict__ xyz, float* __restrict__ new_xyz,
                         int b, int tid) {
    const int lane = tid & 31;
    const float* base = xyz + (size_t)b * NPTS * 3;

    unsigned long long pxp[4], pyp[4], pzp[4];
    float pd[8];
#pragma unroll
    for (int p = 0; p < 4; ++p) {
        int n0 = tid + p * 512;
        int n1 = n0 + 2048;
        pxp[p] = f2_pack(base[n0 * 3 + 0], base[n1 * 3 + 0]);
        pyp[p] = f2_pack(base[n0 * 3 + 1], base[n1 * 3 + 1]);
        pzp[p] = f2_pack(base[n0 * 3 + 2], base[n1 * 3 + 2]);
        pd[p] = 1e10f; pd[p + 4] = 1e10f;
    }

    __shared__ uint2 sWarp[32];   // ping-pong banks of 16

    float cx = __ldg(base + 0), cy = __ldg(base + 1), cz = __ldg(base + 2);
    if (tid == 0) {
        float* o = new_xyz + (size_t)b * NPOINTS * 3;
        o[0] = cx; o[1] = cy; o[2] = cz;
    }

    int bank = 0;
    for (int t = 1; t < NPOINTS; ++t) {
        const unsigned long long ncx2 = f2_pack(-cx, -cx);
        const unsigned long long ncy2 = f2_pack(-cy, -cy);
        const unsigned long long ncz2 = f2_pack(-cz, -cz);
#pragma unroll
        for (int p = 0; p < 4; ++p) {
            unsigned long long dx = f2_add(pxp[p], ncx2);
            unsigned long long dy = f2_add(pyp[p], ncy2);
            unsigned long long dz = f2_add(pzp[p], ncz2);
            unsigned long long s  = f2_add(f2_add(f2_mul(dx, dx), f2_mul(dy, dy)),
                                           f2_mul(dz, dz));
            float lo, hi;
            f2_unpack(s, lo, hi);
            pd[p]     = fminf(pd[p],     lo);
            pd[p + 4] = fminf(pd[p + 4], hi);
        }

        float m0 = fmaxf(pd[0], pd[1]);
        float m1 = fmaxf(pd[2], pd[3]);
        float m2 = fmaxf(pd[4], pd[5]);
        float m3 = fmaxf(pd[6], pd[7]);
        const float bd = fmaxf(fmaxf(m0, m1), fmaxf(m2, m3));

        int bi = 0x7fffffff;
#pragma unroll
        for (int p = 0; p < 4; ++p)
            bi = min(bi, (pd[p] == bd) ? (tid + p * 512) : 0x7fffffff);
#pragma unroll
        for (int p = 0; p < 4; ++p)
            bi = min(bi, (pd[p + 4] == bd) ? (tid + p * 512 + 2048) : 0x7fffffff);

        const unsigned bdb = __float_as_uint(bd);
        const unsigned wd  = __reduce_max_sync(0xffffffffu, bdb);
        const unsigned wi  = __reduce_min_sync(0xffffffffu,
                                (bdb == wd) ? (unsigned)bi : 0xffffffffu);
        if (lane == 0) sWarp[bank * 16 + (tid >> 5)] = make_uint2(wd, wi);
        __syncthreads();

        const uint2 k  = sWarp[bank * 16 + (lane & 15)];
        const unsigned gd = __reduce_max_sync(0xffffffffu, k.x);
        const unsigned gi = __reduce_min_sync(0xffffffffu,
                                (k.x == gd) ? k.y : 0xffffffffu);
        const int idx = (int)gi;
        cx = __ldg(base + idx * 3 + 0);
        cy = __ldg(base + idx * 3 + 1);
        cz = __ldg(base + idx * 3 + 2);
        if (tid == 0) {
            float* o = new_xyz + ((size_t)b * NPOINTS + t) * 3;
            o[0] = cx; o[1] = cy; o[2] = cz;
            if ((t & 3) == 3) st_release(&g_progress[b * 32], t + 1);  // 4-step granule
        }
        bank ^= 1;
    }
}

// ---------------------------------------------------------------------------
// MLP building blocks (identical arithmetic to R8/R9)
// ---------------------------------------------------------------------------
template <int CIN, int COUT, int PIN>
__device__ __forceinline__ void gemm_acc(const float* in_s,
                                         const float* __restrict__ W,
                                         const float* __restrict__ bias,
                                         float acc[4][COUT / 16],
                                         int c, int r) {
    constexpr int JW = COUT / 16;
#pragma unroll
    for (int j = 0; j < JW; ++j) {
        float bj = __ldg(bias + c * JW + j);
#pragma unroll
        for (int m = 0; m < 4; ++m) acc[m][j] = bj;
    }

    const float* wbase = W + c * JW;
    constexpr int CMAIN = CIN & ~3;

    for (int i = 0; i < CMAIN; i += 4) {
        float4 a0 = *(const float4*)(in_s + (r + 0)  * PIN + i);
        float4 a1 = *(const float4*)(in_s + (r + 8)  * PIN + i);
        float4 a2 = *(const float4*)(in_s + (r + 16) * PIN + i);
        float4 a3 = *(const float4*)(in_s + (r + 24) * PIN + i);
        const float av[4][4] = {
            {a0.x, a1.x, a2.x, a3.x},
            {a0.y, a1.y, a2.y, a3.y},
            {a0.z, a1.z, a2.z, a3.z},
            {a0.w, a1.w, a2.w, a3.w}};
#pragma unroll
        for (int u = 0; u < 4; ++u) {
            const float4* wp = (const float4*)(wbase + (i + u) * COUT);
#pragma unroll
            for (int v = 0; v < JW / 4; ++v) {
                float4 w = __ldg(wp + v);
#pragma unroll
                for (int m = 0; m < 4; ++m) {
                    acc[m][v * 4 + 0] = fmaf(av[u][m], w.x, acc[m][v * 4 + 0]);
                    acc[m][v * 4 + 1] = fmaf(av[u][m], w.y, acc[m][v * 4 + 1]);
                    acc[m][v * 4 + 2] = fmaf(av[u][m], w.z, acc[m][v * 4 + 2]);
                    acc[m][v * 4 + 3] = fmaf(av[u][m], w.w, acc[m][v * 4 + 3]);
                }
            }
        }
    }
    for (int i = CMAIN; i < CIN; ++i) {
        float s0 = in_s[(r + 0)  * PIN + i];
        float s1 = in_s[(r + 8)  * PIN + i];
        float s2 = in_s[(r + 16) * PIN + i];
        float s3 = in_s[(r + 24) * PIN + i];
        const float4* wp = (const float4*)(wbase + i * COUT);
#pragma unroll
        for (int v = 0; v < JW / 4; ++v) {
            float4 w = __ldg(wp + v);
#pragma unroll
            for (int q = 0; q < 4; ++q) {
                acc[0][v * 4 + q] = fmaf(s0, ((const float*)&w)[q], acc[0][v * 4 + q]);
                acc[1][v * 4 + q] = fmaf(s1, ((const float*)&w)[q], acc[1][v * 4 + q]);
                acc[2][v * 4 + q] = fmaf(s2, ((const float*)&w)[q], acc[2][v * 4 + q]);
                acc[3][v * 4 + q] = fmaf(s3, ((const float*)&w)[q], acc[3][v * 4 + q]);
            }
        }
    }
}

template <int COUT>
__device__ __forceinline__ void ln_relu_reg(float acc[4][COUT / 16],
                                            const float* __restrict__ g,
                                            const float* __restrict__ be, int c) {
    constexpr int JW = COUT / 16;
    float gv[JW], bv[JW];
#pragma unroll
    for (int j = 0; j < JW; ++j) { gv[j] = __ldg(g + c * JW + j); bv[j] = __ldg(be + c * JW + j); }
#pragma unroll
    for (int m = 0; m < 4; ++m) {
        float sum = 0.0f;
#pragma unroll
        for (int j = 0; j < JW; ++j) sum += acc[m][j];
        sum += __shfl_xor_sync(0xffffffffu, sum, 1);
        sum += __shfl_xor_sync(0xffffffffu, sum, 2);
        sum += __shfl_xor_sync(0xffffffffu, sum, 4);
        sum += __shfl_xor_sync(0xffffffffu, sum, 8);
        const float mu = sum * (1.0f / COUT);
        float sq = 0.0f;
#pragma unroll
        for (int j = 0; j < JW; ++j) { float d = acc[m][j] - mu; sq += d * d; }
        sq += __shfl_xor_sync(0xffffffffu, sq, 1);
        sq += __shfl_xor_sync(0xffffffffu, sq, 2);
        sq += __shfl_xor_sync(0xffffffffu, sq, 4);
        sq += __shfl_xor_sync(0xffffffffu, sq, 8);
        const float inv = rsqrtf(sq * (1.0f / COUT) + 1e-5f);
#pragma unroll
        for (int j = 0; j < JW; ++j)
            acc[m][j] = fmaxf((acc[m][j] - mu) * inv * gv[j] + bv[j], 0.0f);
    }
}

template <int COUT, int POUT>
__device__ __forceinline__ void store_rows(const float acc[4][COUT / 16],
                                           float* out_s, int c, int r) {
    constexpr int JW = COUT / 16;
#pragma unroll
    for (int m = 0; m < 4; ++m)
#pragma unroll
        for (int v = 0; v < JW / 4; ++v)
            *(float4*)(out_s + (r + 8 * m) * POUT + c * JW + v * 4) =
                make_float4(acc[m][v * 4 + 0], acc[m][v * 4 + 1],
                            acc[m][v * 4 + 2], acc[m][v * 4 + 3]);
}

// ---------------------------------------------------------------------------
// Worker role: 4 groups of 128 threads; each group = one (b,s) pipeline.
// ---------------------------------------------------------------------------
__device__ void worker_role(const float* __restrict__ xyz,
                            const float* __restrict__ points,
                            const float* __restrict__ new_xyz,
                            const float* __restrict__ W1, const float* __restrict__ b1,
                            const float* __restrict__ g1, const float* __restrict__ be1,
                            const float* __restrict__ W2, const float* __restrict__ b2,
                            const float* __restrict__ g2, const float* __restrict__ be2,
                            const float* __restrict__ W3, const float* __restrict__ b3,
                            const float* __restrict__ g3, const float* __restrict__ be3,
                            float* __restrict__ new_points,
                            float* smem, int wb, int tid) {
    const int b = wb % BATCH;           // batch
    const int w = wb / BATCH;           // 0..NW_PER_B-1 worker index within batch
    const int grp  = tid >> 7;          // 0..3
    const int gtid = tid & 127;
    const int c = gtid & 15;
    const int r = gtid >> 4;

    float* sxyz = smem;                         // 12288 floats
    float* gbase = smem + SXYZ_F + grp * GRP_F;
    float* bufA  = gbase;                       // 32*68
    float* bufB  = gbase + 32 * PIN_A;          // 32*132
    int*   sIdx  = (int*)(smem + SXYZ_F + 4 * GRP_F);   // 128 ints (32 per group)
    float* sCen  = (float*)(sIdx + 128);                 // 16 floats (4 per group)

    // stage batch xyz into smem (immutable input)
    {
        const float4* src = (const float4*)(xyz + (size_t)b * NPTS * 3);
        for (int i = tid; i < SXYZ_F / 4; i += 512)
            ((float4*)sxyz)[i] = src[i];
    }
    __syncthreads();

    for (int base = w * 4; base < NPOINTS; base += NW_PER_B * 4) {
        const int s = base + grp;
        // ---- pace on producer (padded line, backoff poll) ----
        if (tid == 0) {
            const int need = min(base + 4, NPOINTS);
            while (ld_acquire(&g_progress[b * 32]) < need) __nanosleep(100);
        }
        __syncthreads();

        // ---- ball query: warp 0 of each group ----
        if (gtid < 32) {
            const int lane = gtid;
            const float* cp = new_xyz + ((size_t)b * NPOINTS + s) * 3;
            const float cx = __ldcg(cp + 0);   // L2-only: line may be stale in L1
            const float cy = __ldcg(cp + 1);
            const float cz = __ldcg(cp + 2);
            if (lane < 3) sCen[grp * 4 + lane] = __ldcg(cp + lane);
            const float R2 = (float)(0.2 * 0.2);
            int* out = sIdx + grp * 32;
            int cnt = 0, first = -1;
            for (int rr = 0; rr < NPTS / 32; ++rr) {
                int n = rr * 32 + lane;
                float d = sqd_nofma(sxyz[n * 3], sxyz[n * 3 + 1], sxyz[n * 3 + 2],
                                    cx, cy, cz);
                bool ok = !(d > R2);
                unsigned m = __ballot_sync(0xffffffffu, ok);
                if (first < 0 && m) first = rr * 32 + (__ffs(m) - 1);
                if (ok) {
                    int pos = cnt + __popc(m & ((1u << lane) - 1u));
                    if (pos < NSAMPLE) out[pos] = n;
                }
                cnt += __popc(m);
                if (cnt >= NSAMPLE) break;
            }
            if (cnt < NSAMPLE && lane >= cnt && lane < NSAMPLE) out[lane] = first;
        }
        __syncthreads();

        // ---- gather: 4 threads per sample ----
        {
            const int k = gtid >> 2, q = gtid & 3;
            const int n = sIdx[grp * 32 + k];
            const float4* prow = (const float4*)(points + ((size_t)b * NPTS + n) * 64) + q * 4;
            float* dst = bufA + k * PIN_A + 3 + q * 16;
#pragma unroll
            for (int v = 0; v < 4; ++v) {
                float4 f = __ldg(prow + v);
                dst[v * 4 + 0] = f.x;
                dst[v * 4 + 1] = f.y;
                dst[v * 4 + 2] = f.z;
                dst[v * 4 + 3] = f.w;
            }
            if (q == 0) {
                bufA[k * PIN_A + 0] = sxyz[n * 3 + 0] - sCen[grp * 4 + 0];
                bufA[k * PIN_A + 1] = sxyz[n * 3 + 1] - sCen[grp * 4 + 1];
                bufA[k * PIN_A + 2] = sxyz[n * 3 + 2] - sCen[grp * 4 + 2];
            }
        }
        __syncthreads();

        {   // layer 1: 67 -> 64
            float acc[4][4];
            gemm_acc<67, 64, PIN_A>(bufA, W1, b1, acc, c, r);
            ln_relu_reg<64>(acc, g1, be1, c);
            store_rows<64, PIN_B>(acc, bufB, c, r);
        }
        __syncthreads();

        {   // layer 2: 64 -> 64
            float acc[4][4];
            gemm_acc<64, 64, PIN_B>(bufB, W2, b2, acc, c, r);
            ln_relu_reg<64>(acc, g2, be2, c);
            store_rows<64, PIN_A>(acc, bufA, c, r);
        }
        __syncthreads();

        {   // layer 3: 64 -> 128, fused partial max over 4 samples
            float acc[4][8];
            gemm_acc<64, 128, PIN_A>(bufA, W3, b3, acc, c, r);
            ln_relu_reg<128>(acc, g3, be3, c);
#pragma unroll
            for (int j = 0; j < 8; ++j) {
                float pm = fmaxf(fmaxf(acc[0][j], acc[1][j]), fmaxf(acc[2][j], acc[3][j]));
                bufB[r * PIN_B + c * 8 + j] = pm;
            }
        }
        __syncthreads();

        {   // final max over 8 r-partials; relu >= 0 so init 0 exact
            float m = 0.0f;
#pragma unroll
            for (int k = 0; k < 8; ++k) m = fmaxf(m, bufB[k * PIN_B + gtid]);
            new_points[((size_t)b * NPOINTS + s) * 128 + gtid] = m;
        }
        __syncthreads();   // protect bufs before next iteration's gather
    }
}

// ---------------------------------------------------------------------------
__global__ __launch_bounds__(512, 1) void fused_kernel(
    const float* __restrict__ xyz, const float* __restrict__ points,
    const float* __restrict__ W1, const float* __restrict__ b1,
    const float* __restrict__ g1, const float* __restrict__ be1,
    const float* __restrict__ W2, const float* __restrict__ b2,
    const float* __restrict__ g2, const float* __restrict__ be2,
    const float* __restrict__ W3, const float* __restrict__ b3,
    const float* __restrict__ g3, const float* __restrict__ be3,
    float* __restrict__ new_xyz, float* __restrict__ new_points) {
    extern __shared__ float smem[];
    const int tid = threadIdx.x;
    if (blockIdx.x < BATCH) {
        fps_role(xyz, new_xyz, blockIdx.x, tid);
    } else {
        worker_role(xyz, points, new_xyz,
                    W1, b1, g1, be1, W2, b2, g2, be2, W3, b3, g3, be3,
                    new_points, smem, blockIdx.x - BATCH, tid);
    }
}

// ---------------------------------------------------------------------------
extern "C" void kernel_launch(void* const* d_in, const int* in_sizes, int n_in,
                              void* d_out, int out_size) {
    (void)in_sizes; (void)n_in; (void)out_size;
    const float* xyz    = (const float*)d_in[0];
    const float* points = (const float*)d_in[1];
    const float* W1  = (const float*)d_in[2];
    const float* b1  = (const float*)d_in[3];
    const float* g1  = (const float*)d_in[4];
    const float* be1 = (const float*)d_in[5];
    const float* W2  = (const float*)d_in[6];
    const float* b2  = (const float*)d_in[7];
    const float* g2  = (const float*)d_in[8];
    const float* be2 = (const float*)d_in[9];
    const float* W3  = (const float*)d_in[10];
    const float* b3  = (const float*)d_in[11];
    const float* g3  = (const float*)d_in[12];
    const float* be3 = (const float*)d_in[13];

    float* out        = (float*)d_out;
    float* new_xyz    = out;                          // [8,1024,3]
    float* new_points = out + BATCH * NPOINTS * 3;    // [8,1024,128]

    cudaFuncSetAttribute(fused_kernel, cudaFuncAttributeMaxDynamicSharedMemorySize,
                         SMEM_DYN);

    reset_kernel<<<1, 256>>>();
    fused_kernel<<<NBLOCKS, 512, SMEM_DYN>>>(xyz, points,
                                             W1, b1, g1, be1,
                                             W2, b2, g2, be2,
                                             W3, b3, g3, be3,
                                             new_xyz, new_points);
}

// round 12
// speedup vs baseline: 2.0740x; 1.1334x over previous
#include <cuda_runtime.h>

#define BATCH   8
#define NPTS    4096
#define NPOINTS 1024
#define NSAMPLE 32
#define PIN_A   68
#define PIN_B   132
#define NW_PER_B 17                    // worker blocks per batch
#define NWORKERS (NW_PER_B * BATCH)    // 136
#define NBLOCKS  (BATCH + NWORKERS)    // 144 <= 148 SMs -> all resident wave 1

#define SXYZ_F   (NPTS * 3)                    // 12288 floats
#define GRP_F    (32 * PIN_A + 32 * PIN_B)     // 6400 floats per group
#define SMEM_DYN ((SXYZ_F + 4 * GRP_F) * 4 + 128 * 4 + 16 * 4)  // 152128 B

// progress[b*32] = number of centroids of batch b published (128B line per batch)
__device__ int g_progress[BATCH * 32];

// ---------------------------------------------------------------------------
__device__ __forceinline__ float sqd_nofma(float x, float y, float z,
                                           float cx, float cy, float cz) {
    float dx = x - cx, dy = y - cy, dz = z - cz;
    return __fadd_rn(__fadd_rn(__fmul_rn(dx, dx), __fmul_rn(dy, dy)), __fmul_rn(dz, dz));
}

__device__ __forceinline__ unsigned long long f2_add(unsigned long long a, unsigned long long b) {
    unsigned long long r;
    asm("add.rn.f32x2 %0, %1, %2;" : "=l"(r) : "l"(a), "l"(b));
    return r;
}
__device__ __forceinline__ unsigned long long f2_mul(unsigned long long a, unsigned long long b) {
    unsigned long long r;
    asm("mul.rn.f32x2 %0, %1, %2;" : "=l"(r) : "l"(a), "l"(b));
    return r;
}
__device__ __forceinline__ unsigned long long f2_pack(float lo, float hi) {
    unsigned long long r;
    asm("mov.b64 %0, {%1, %2};" : "=l"(r) : "f"(lo), "f"(hi));
    return r;
}
__device__ __forceinline__ void f2_unpack(unsigned long long v, float& lo, float& hi) {
    asm("mov.b64 {%0, %1}, %2;" : "=f"(lo), "=f"(hi) : "l"(v));
}

__device__ __forceinline__ int ld_acquire(const int* p) {
    int v;
    asm volatile("ld.acquire.gpu.global.s32 %0, [%1];" : "=r"(v) : "l"(p) : "memory");
    return v;
}
__device__ __forceinline__ void st_release(int* p, int v) {
    asm volatile("st.release.gpu.global.s32 [%0], %1;" :: "l"(p), "r"(v) : "memory");
}

// 128-thread named barrier for group decoupling (ids 1..4; 0 = __syncthreads)
__device__ __forceinline__ void bar_grp(int id) {
    asm volatile("bar.sync %0, 128;" :: "r"(id) : "memory");
}

// ---------------------------------------------------------------------------
__global__ void reset_kernel() {
    if (threadIdx.x < BATCH * 32) g_progress[threadIdx.x] = 0;
}

// ---------------------------------------------------------------------------
// FPS role (blocks 0..7): identical selection math; progress published every
// 4 steps.
// ---------------------------------------------------------------------------
__device__ void fps_role(const float* __restrict__ xyz, float* __restrict__ new_xyz,
                         int b, int tid) {
    const int lane = tid & 31;
    const float* base = xyz + (size_t)b * NPTS * 3;

    unsigned long long pxp[4], pyp[4], pzp[4];
    float pd[8];
#pragma unroll
    for (int p = 0; p < 4; ++p) {
        int n0 = tid + p * 512;
        int n1 = n0 + 2048;
        pxp[p] = f2_pack(base[n0 * 3 + 0], base[n1 * 3 + 0]);
        pyp[p] = f2_pack(base[n0 * 3 + 1], base[n1 * 3 + 1]);
        pzp[p] = f2_pack(base[n0 * 3 + 2], base[n1 * 3 + 2]);
        pd[p] = 1e10f; pd[p + 4] = 1e10f;
    }

    __shared__ uint2 sWarp[32];   // ping-pong banks of 16

    float cx = __ldg(base + 0), cy = __ldg(base + 1), cz = __ldg(base + 2);
    if (tid == 0) {
        float* o = new_xyz + (size_t)b * NPOINTS * 3;
        o[0] = cx; o[1] = cy; o[2] = cz;
    }

    int bank = 0;
    for (int t = 1; t < NPOINTS; ++t) {
        const unsigned long long ncx2 = f2_pack(-cx, -cx);
        const unsigned long long ncy2 = f2_pack(-cy, -cy);
        const unsigned long long ncz2 = f2_pack(-cz, -cz);
#pragma unroll
        for (int p = 0; p < 4; ++p) {
            unsigned long long dx = f2_add(pxp[p], ncx2);
            unsigned long long dy = f2_add(pyp[p], ncy2);
            unsigned long long dz = f2_add(pzp[p], ncz2);
            unsigned long long s  = f2_add(f2_add(f2_mul(dx, dx), f2_mul(dy, dy)),
                                           f2_mul(dz, dz));
            float lo, hi;
            f2_unpack(s, lo, hi);
            pd[p]     = fminf(pd[p],     lo);
            pd[p + 4] = fminf(pd[p + 4], hi);
        }

        float m0 = fmaxf(pd[0], pd[1]);
        float m1 = fmaxf(pd[2], pd[3]);
        float m2 = fmaxf(pd[4], pd[5]);
        float m3 = fmaxf(pd[6], pd[7]);
        const float bd = fmaxf(fmaxf(m0, m1), fmaxf(m2, m3));

        int bi = 0x7fffffff;
#pragma unroll
        for (int p = 0; p < 4; ++p)
            bi = min(bi, (pd[p] == bd) ? (tid + p * 512) : 0x7fffffff);
#pragma unroll
        for (int p = 0; p < 4; ++p)
            bi = min(bi, (pd[p + 4] == bd) ? (tid + p * 512 + 2048) : 0x7fffffff);

        const unsigned bdb = __float_as_uint(bd);
        const unsigned wd  = __reduce_max_sync(0xffffffffu, bdb);
        const unsigned wi  = __reduce_min_sync(0xffffffffu,
                                (bdb == wd) ? (unsigned)bi : 0xffffffffu);
        if (lane == 0) sWarp[bank * 16 + (tid >> 5)] = make_uint2(wd, wi);
        __syncthreads();

        const uint2 k  = sWarp[bank * 16 + (lane & 15)];
        const unsigned gd = __reduce_max_sync(0xffffffffu, k.x);
        const unsigned gi = __reduce_min_sync(0xffffffffu,
                                (k.x == gd) ? k.y : 0xffffffffu);
        const int idx = (int)gi;
        cx = __ldg(base + idx * 3 + 0);
        cy = __ldg(base + idx * 3 + 1);
        cz = __ldg(base + idx * 3 + 2);
        if (tid == 0) {
            float* o = new_xyz + ((size_t)b * NPOINTS + t) * 3;
            o[0] = cx; o[1] = cy; o[2] = cz;
            if ((t & 3) == 3) st_release(&g_progress[b * 32], t + 1);  // 4-step granule
        }
        bank ^= 1;
    }
}

// ---------------------------------------------------------------------------
// MLP building blocks (identical arithmetic to R8-R10)
// ---------------------------------------------------------------------------
template <int CIN, int COUT, int PIN>
__device__ __forceinline__ void gemm_acc(const float* in_s,
                                         const float* __restrict__ W,
                                         const float* __restrict__ bias,
                                         float acc[4][COUT / 16],
                                         int c, int r) {
    constexpr int JW = COUT / 16;
#pragma unroll
    for (int j = 0; j < JW; ++j) {
        float bj = __ldg(bias + c * JW + j);
#pragma unroll
        for (int m = 0; m < 4; ++m) acc[m][j] = bj;
    }

    const float* wbase = W + c * JW;
    constexpr int CMAIN = CIN & ~3;

    for (int i = 0; i < CMAIN; i += 4) {
        float4 a0 = *(const float4*)(in_s + (r + 0)  * PIN + i);
        float4 a1 = *(const float4*)(in_s + (r + 8)  * PIN + i);
        float4 a2 = *(const float4*)(in_s + (r + 16) * PIN + i);
        float4 a3 = *(const float4*)(in_s + (r + 24) * PIN + i);
        const float av[4][4] = {
            {a0.x, a1.x, a2.x, a3.x},
            {a0.y, a1.y, a2.y, a3.y},
            {a0.z, a1.z, a2.z, a3.z},
            {a0.w, a1.w, a2.w, a3.w}};
#pragma unroll
        for (int u = 0; u < 4; ++u) {
            const float4* wp = (const float4*)(wbase + (i + u) * COUT);
#pragma unroll
            for (int v = 0; v < JW / 4; ++v) {
                float4 w = __ldg(wp + v);
#pragma unroll
                for (int m = 0; m < 4; ++m) {
                    acc[m][v * 4 + 0] = fmaf(av[u][m], w.x, acc[m][v * 4 + 0]);
                    acc[m][v * 4 + 1] = fmaf(av[u][m], w.y, acc[m][v * 4 + 1]);
                    acc[m][v * 4 + 2] = fmaf(av[u][m], w.z, acc[m][v * 4 + 2]);
                    acc[m][v * 4 + 3] = fmaf(av[u][m], w.w, acc[m][v * 4 + 3]);
                }
            }
        }
    }
    for (int i = CMAIN; i < CIN; ++i) {
        float s0 = in_s[(r + 0)  * PIN + i];
        float s1 = in_s[(r + 8)  * PIN + i];
        float s2 = in_s[(r + 16) * PIN + i];
        float s3 = in_s[(r + 24) * PIN + i];
        const float4* wp = (const float4*)(wbase + i * COUT);
#pragma unroll
        for (int v = 0; v < JW / 4; ++v) {
            float4 w = __ldg(wp + v);
#pragma unroll
            for (int q = 0; q < 4; ++q) {
                acc[0][v * 4 + q] = fmaf(s0, ((const float*)&w)[q], acc[0][v * 4 + q]);
                acc[1][v * 4 + q] = fmaf(s1, ((const float*)&w)[q], acc[1][v * 4 + q]);
                acc[2][v * 4 + q] = fmaf(s2, ((const float*)&w)[q], acc[2][v * 4 + q]);
                acc[3][v * 4 + q] = fmaf(s3, ((const float*)&w)[q], acc[3][v * 4 + q]);
            }
        }
    }
}

template <int COUT>
__device__ __forceinline__ void ln_relu_reg(float acc[4][COUT / 16],
                                            const float* __restrict__ g,
                                            const float* __restrict__ be, int c) {
    constexpr int JW = COUT / 16;
    float gv[JW], bv[JW];
#pragma unroll
    for (int j = 0; j < JW; ++j) { gv[j] = __ldg(g + c * JW + j); bv[j] = __ldg(be + c * JW + j); }
#pragma unroll
    for (int m = 0; m < 4; ++m) {
        float sum = 0.0f;
#pragma unroll
        for (int j = 0; j < JW; ++j) sum += acc[m][j];
        sum += __shfl_xor_sync(0xffffffffu, sum, 1);
        sum += __shfl_xor_sync(0xffffffffu, sum, 2);
        sum += __shfl_xor_sync(0xffffffffu, sum, 4);
        sum += __shfl_xor_sync(0xffffffffu, sum, 8);
        const float mu = sum * (1.0f / COUT);
        float sq = 0.0f;
#pragma unroll
        for (int j = 0; j < JW; ++j) { float d = acc[m][j] - mu; sq += d * d; }
        sq += __shfl_xor_sync(0xffffffffu, sq, 1);
        sq += __shfl_xor_sync(0xffffffffu, sq, 2);
        sq += __shfl_xor_sync(0xffffffffu, sq, 4);
        sq += __shfl_xor_sync(0xffffffffu, sq, 8);
        const float inv = rsqrtf(sq * (1.0f / COUT) + 1e-5f);
#pragma unroll
        for (int j = 0; j < JW; ++j)
            acc[m][j] = fmaxf((acc[m][j] - mu) * inv * gv[j] + bv[j], 0.0f);
    }
}

template <int COUT, int POUT>
__device__ __forceinline__ void store_rows(const float acc[4][COUT / 16],
                                           float* out_s, int c, int r) {
    constexpr int JW = COUT / 16;
#pragma unroll
    for (int m = 0; m < 4; ++m)
#pragma unroll
        for (int v = 0; v < JW / 4; ++v)
            *(float4*)(out_s + (r + 8 * m) * POUT + c * JW + v * 4) =
                make_float4(acc[m][v * 4 + 0], acc[m][v * 4 + 1],
                            acc[m][v * 4 + 2], acc[m][v * 4 + 3]);
}

// ---------------------------------------------------------------------------
// Worker role: 4 groups of 128 threads, DECOUPLED via named barriers
// (ids 1..4). Each group paces, ball-queries, gathers, and runs the MLP
// independently — per-SMSP, warps from 4 out-of-phase groups hide each
// other's barrier/LN latency.
// ---------------------------------------------------------------------------
__device__ void worker_role(const float* __restrict__ xyz,
                            const float* __restrict__ points,
                            const float* __restrict__ new_xyz,
                            const float* __restrict__ W1, const float* __restrict__ b1,
                            const float* __restrict__ g1, const float* __restrict__ be1,
                            const float* __restrict__ W2, const float* __restrict__ b2,
                            const float* __restrict__ g2, const float* __restrict__ be2,
                            const float* __restrict__ W3, const float* __restrict__ b3,
                            const float* __restrict__ g3, const float* __restrict__ be3,
                            float* __restrict__ new_points,
                            float* smem, int wb, int tid) {
    const int b = wb % BATCH;           // batch
    const int w = wb / BATCH;           // 0..NW_PER_B-1 worker index within batch
    const int grp  = tid >> 7;          // 0..3
    const int gtid = tid & 127;
    const int c = gtid & 15;
    const int r = gtid >> 4;
    const int bid = grp + 1;            // named barrier id for this group

    float* sxyz = smem;                         // 12288 floats
    float* gbase = smem + SXYZ_F + grp * GRP_F;
    float* bufA  = gbase;                       // 32*68
    float* bufB  = gbase + 32 * PIN_A;          // 32*132
    int*   sIdx  = (int*)(smem + SXYZ_F + 4 * GRP_F) + grp * 32;
    float* sCen  = (float*)((int*)(smem + SXYZ_F + 4 * GRP_F) + 128) + grp * 4;

    // stage batch xyz into smem (immutable input) — one block-wide barrier
    {
        const float4* src = (const float4*)(xyz + (size_t)b * NPTS * 3);
        for (int i = tid; i < SXYZ_F / 4; i += 512)
            ((float4*)sxyz)[i] = src[i];
    }
    __syncthreads();

    for (int base = w * 4; base < NPOINTS; base += NW_PER_B * 4) {
        const int s = base + grp;
        // ---- pace on producer: this group's centroid only ----
        if (gtid == 0) {
            while (ld_acquire(&g_progress[b * 32]) < s + 1) __nanosleep(100);
        }
        bar_grp(bid);

        // ---- ball query: warp 0 of the group ----
        if (gtid < 32) {
            const int lane = gtid;
            const float* cp = new_xyz + ((size_t)b * NPOINTS + s) * 3;
            const float cx = __ldcg(cp + 0);   // L2-only: line may be stale in L1
            const float cy = __ldcg(cp + 1);
            const float cz = __ldcg(cp + 2);
            if (lane < 3) sCen[lane] = __ldcg(cp + lane);
            const float R2 = (float)(0.2 * 0.2);
            int cnt = 0, first = -1;
            for (int rr = 0; rr < NPTS / 32; ++rr) {
                int n = rr * 32 + lane;
                float d = sqd_nofma(sxyz[n * 3], sxyz[n * 3 + 1], sxyz[n * 3 + 2],
                                    cx, cy, cz);
                bool ok = !(d > R2);
                unsigned m = __ballot_sync(0xffffffffu, ok);
                if (first < 0 && m) first = rr * 32 + (__ffs(m) - 1);
                if (ok) {
                    int pos = cnt + __popc(m & ((1u << lane) - 1u));
                    if (pos < NSAMPLE) sIdx[pos] = n;
                }
                cnt += __popc(m);
                if (cnt >= NSAMPLE) break;
            }
            if (cnt < NSAMPLE && lane >= cnt && lane < NSAMPLE) sIdx[lane] = first;
        }
        bar_grp(bid);

        // ---- gather: 4 threads per sample ----
        {
            const int k = gtid >> 2, q = gtid & 3;
            const int n = sIdx[k];
            const float4* prow = (const float4*)(points + ((size_t)b * NPTS + n) * 64) + q * 4;
            float* dst = bufA + k * PIN_A + 3 + q * 16;
#pragma unroll
            for (int v = 0; v < 4; ++v) {
                float4 f = __ldg(prow + v);
                dst[v * 4 + 0] = f.x;
                dst[v * 4 + 1] = f.y;
                dst[v * 4 + 2] = f.z;
                dst[v * 4 + 3] = f.w;
            }
            if (q == 0) {
                bufA[k * PIN_A + 0] = sxyz[n * 3 + 0] - sCen[0];
                bufA[k * PIN_A + 1] = sxyz[n * 3 + 1] - sCen[1];
                bufA[k * PIN_A + 2] = sxyz[n * 3 + 2] - sCen[2];
            }
        }
        bar_grp(bid);

        {   // layer 1: 67 -> 64
            float acc[4][4];
            gemm_acc<67, 64, PIN_A>(bufA, W1, b1, acc, c, r);
            ln_relu_reg<64>(acc, g1, be1, c);
            store_rows<64, PIN_B>(acc, bufB, c, r);
        }
        bar_grp(bid);

        {   // layer 2: 64 -> 64
            float acc[4][4];
            gemm_acc<64, 64, PIN_B>(bufB, W2, b2, acc, c, r);
            ln_relu_reg<64>(acc, g2, be2, c);
            store_rows<64, PIN_A>(acc, bufA, c, r);
        }
        bar_grp(bid);

        {   // layer 3: 64 -> 128, fused partial max over 4 samples
            float acc[4][8];
            gemm_acc<64, 128, PIN_A>(bufA, W3, b3, acc, c, r);
            ln_relu_reg<128>(acc, g3, be3, c);
#pragma unroll
            for (int j = 0; j < 8; ++j) {
                float pm = fmaxf(fmaxf(acc[0][j], acc[1][j]), fmaxf(acc[2][j], acc[3][j]));
                bufB[r * PIN_B + c * 8 + j] = pm;
            }
        }
        bar_grp(bid);

        {   // final max over 8 r-partials; relu >= 0 so init 0 exact
            float m = 0.0f;
#pragma unroll
            for (int k = 0; k < 8; ++k) m = fmaxf(m, bufB[k * PIN_B + gtid]);
            new_points[((size_t)b * NPOINTS + s) * 128 + gtid] = m;
        }
        bar_grp(bid);   // protect bufs before next iteration's gather
    }
}

// ---------------------------------------------------------------------------
__global__ __launch_bounds__(512, 1) void fused_kernel(
    const float* __restrict__ xyz, const float* __restrict__ points,
    const float* __restrict__ W1, const float* __restrict__ b1,
    const float* __restrict__ g1, const float* __restrict__ be1,
    const float* __restrict__ W2, const float* __restrict__ b2,
    const float* __restrict__ g2, const float* __restrict__ be2,
    const float* __restrict__ W3, const float* __restrict__ b3,
    const float* __restrict__ g3, const float* __restrict__ be3,
    float* __restrict__ new_xyz, float* __restrict__ new_points) {
    extern __shared__ float smem[];
    const int tid = threadIdx.x;
    if (blockIdx.x < BATCH) {
        fps_role(xyz, new_xyz, blockIdx.x, tid);
    } else {
        worker_role(xyz, points, new_xyz,
                    W1, b1, g1, be1, W2, b2, g2, be2, W3, b3, g3, be3,
                    new_points, smem, blockIdx.x - BATCH, tid);
    }
}

// ---------------------------------------------------------------------------
extern "C" void kernel_launch(void* const* d_in, const int* in_sizes, int n_in,
                              void* d_out, int out_size) {
    (void)in_sizes; (void)n_in; (void)out_size;
    const float* xyz    = (const float*)d_in[0];
    const float* points = (const float*)d_in[1];
    const float* W1  = (const float*)d_in[2];
    const float* b1  = (const float*)d_in[3];
    const float* g1  = (const float*)d_in[4];
    const float* be1 = (const float*)d_in[5];
    const float* W2  = (const float*)d_in[6];
    const float* b2  = (const float*)d_in[7];
    const float* g2  = (const float*)d_in[8];
    const float* be2 = (const float*)d_in[9];
    const float* W3  = (const float*)d_in[10];
    const float* b3  = (const float*)d_in[11];
    const float* g3  = (const float*)d_in[12];
    const float* be3 = (const float*)d_in[13];

    float* out        = (float*)d_out;
    float* new_xyz    = out;                          // [8,1024,3]
    float* new_points = out + BATCH * NPOINTS * 3;    // [8,1024,128]

    cudaFuncSetAttribute(fused_kernel, cudaFuncAttributeMaxDynamicSharedMemorySize,
                         SMEM_DYN);

    reset_kernel<<<1, 256>>>();
    fused_kernel<<<NBLOCKS, 512, SMEM_DYN>>>(xyz, points,
                                             W1, b1, g1, be1,
                                             W2, b2, g2, be2,
                                             W3, b3, g3, be3,
                                             new_xyz, new_points);
}

// round 13
// speedup vs baseline: 2.0757x; 1.0008x over previous
#include <cuda_runtime.h>

#define BATCH   8
#define NPTS    4096
#define NPOINTS 1024
#define NSAMPLE 32
#define PIN_A   68
#define PIN_B   132
#define NW_PER_B 17                    // worker blocks per batch
#define NWORKERS (NW_PER_B * BATCH)    // 136
#define NBLOCKS  (BATCH + NWORKERS)    // 144 <= 148 SMs -> all resident wave 1
#define NGRP     5                     // pipelines per worker block
#define THREADS  (NGRP * 128)          // 640

#define SXYZ_F   (NPTS * 3)                    // 12288 floats
#define GRP_F    (32 * PIN_A + 32 * PIN_B)     // 6400 floats per group
#define SMEM_DYN ((SXYZ_F + NGRP * GRP_F) * 4 + NGRP * 32 * 4 + NGRP * 4 * 4)

// progress[b*32] = number of centroids of batch b published (128B line per batch)
__device__ int g_progress[BATCH * 32];

// ---------------------------------------------------------------------------
__device__ __forceinline__ float sqd_nofma(float x, float y, float z,
                                           float cx, float cy, float cz) {
    float dx = x - cx, dy = y - cy, dz = z - cz;
    return __fadd_rn(__fadd_rn(__fmul_rn(dx, dx), __fmul_rn(dy, dy)), __fmul_rn(dz, dz));
}

__device__ __forceinline__ unsigned long long f2_add(unsigned long long a, unsigned long long b) {
    unsigned long long r;
    asm("add.rn.f32x2 %0, %1, %2;" : "=l"(r) : "l"(a), "l"(b));
    return r;
}
__device__ __forceinline__ unsigned long long f2_mul(unsigned long long a, unsigned long long b) {
    unsigned long long r;
    asm("mul.rn.f32x2 %0, %1, %2;" : "=l"(r) : "l"(a), "l"(b));
    return r;
}
__device__ __forceinline__ unsigned long long f2_pack(float lo, float hi) {
    unsigned long long r;
    asm("mov.b64 %0, {%1, %2};" : "=l"(r) : "f"(lo), "f"(hi));
    return r;
}
__device__ __forceinline__ void f2_unpack(unsigned long long v, float& lo, float& hi) {
    asm("mov.b64 {%0, %1}, %2;" : "=f"(lo), "=f"(hi) : "l"(v));
}

__device__ __forceinline__ int ld_acquire(const int* p) {
    int v;
    asm volatile("ld.acquire.gpu.global.s32 %0, [%1];" : "=r"(v) : "l"(p) : "memory");
    return v;
}
__device__ __forceinline__ void st_release(int* p, int v) {
    asm volatile("st.release.gpu.global.s32 [%0], %1;" :: "l"(p), "r"(v) : "memory");
}

// 128-thread named barrier for group decoupling (ids 1..NGRP)
__device__ __forceinline__ void bar_grp(int id) {
    asm volatile("bar.sync %0, 128;" :: "r"(id) : "memory");
}

// ---------------------------------------------------------------------------
__global__ void reset_kernel() {
    if (threadIdx.x < BATCH * 32) g_progress[threadIdx.x] = 0;
}

// ---------------------------------------------------------------------------
// FPS role (blocks 0..7): 512 active threads; threads 512..639 are
// barrier-only participants (identical __syncthreads count, no math -> the
// selection sequence is bit-identical to R7-R12).
// ---------------------------------------------------------------------------
__device__ void fps_role(const float* __restrict__ xyz, float* __restrict__ new_xyz,
                         int b, int tid) {
    const int lane = tid & 31;
    const bool active = (tid < 512);
    const float* base = xyz + (size_t)b * NPTS * 3;

    unsigned long long pxp[4], pyp[4], pzp[4];
    float pd[8];
    if (active) {
#pragma unroll
        for (int p = 0; p < 4; ++p) {
            int n0 = tid + p * 512;
            int n1 = n0 + 2048;
            pxp[p] = f2_pack(base[n0 * 3 + 0], base[n1 * 3 + 0]);
            pyp[p] = f2_pack(base[n0 * 3 + 1], base[n1 * 3 + 1]);
            pzp[p] = f2_pack(base[n0 * 3 + 2], base[n1 * 3 + 2]);
            pd[p] = 1e10f; pd[p + 4] = 1e10f;
        }
    }

    __shared__ uint2 sWarp[32];   // ping-pong banks of 16

    float cx = __ldg(base + 0), cy = __ldg(base + 1), cz = __ldg(base + 2);
    if (tid == 0) {
        float* o = new_xyz + (size_t)b * NPOINTS * 3;
        o[0] = cx; o[1] = cy; o[2] = cz;
    }

    int bank = 0;
    for (int t = 1; t < NPOINTS; ++t) {
        if (active) {
            const unsigned long long ncx2 = f2_pack(-cx, -cx);
            const unsigned long long ncy2 = f2_pack(-cy, -cy);
            const unsigned long long ncz2 = f2_pack(-cz, -cz);
#pragma unroll
            for (int p = 0; p < 4; ++p) {
                unsigned long long dx = f2_add(pxp[p], ncx2);
                unsigned long long dy = f2_add(pyp[p], ncy2);
                unsigned long long dz = f2_add(pzp[p], ncz2);
                unsigned long long s  = f2_add(f2_add(f2_mul(dx, dx), f2_mul(dy, dy)),
                                               f2_mul(dz, dz));
                float lo, hi;
                f2_unpack(s, lo, hi);
                pd[p]     = fminf(pd[p],     lo);
                pd[p + 4] = fminf(pd[p + 4], hi);
            }

            float m0 = fmaxf(pd[0], pd[1]);
            float m1 = fmaxf(pd[2], pd[3]);
            float m2 = fmaxf(pd[4], pd[5]);
            float m3 = fmaxf(pd[6], pd[7]);
            const float bd = fmaxf(fmaxf(m0, m1), fmaxf(m2, m3));

            int bi = 0x7fffffff;
#pragma unroll
            for (int p = 0; p < 4; ++p)
                bi = min(bi, (pd[p] == bd) ? (tid + p * 512) : 0x7fffffff);
#pragma unroll
            for (int p = 0; p < 4; ++p)
                bi = min(bi, (pd[p + 4] == bd) ? (tid + p * 512 + 2048) : 0x7fffffff);

            const unsigned bdb = __float_as_uint(bd);
            const unsigned wd  = __reduce_max_sync(0xffffffffu, bdb);
            const unsigned wi  = __reduce_min_sync(0xffffffffu,
                                    (bdb == wd) ? (unsigned)bi : 0xffffffffu);
            if (lane == 0) sWarp[bank * 16 + (tid >> 5)] = make_uint2(wd, wi);
        }
        __syncthreads();

        if (active) {
            const uint2 k  = sWarp[bank * 16 + (lane & 15)];
            const unsigned gd = __reduce_max_sync(0xffffffffu, k.x);
            const unsigned gi = __reduce_min_sync(0xffffffffu,
                                    (k.x == gd) ? k.y : 0xffffffffu);
            const int idx = (int)gi;
            cx = __ldg(base + idx * 3 + 0);
            cy = __ldg(base + idx * 3 + 1);
            cz = __ldg(base + idx * 3 + 2);
            if (tid == 0) {
                float* o = new_xyz + ((size_t)b * NPOINTS + t) * 3;
                o[0] = cx; o[1] = cy; o[2] = cz;
                if ((t & 3) == 3) st_release(&g_progress[b * 32], t + 1);
            }
        }
        bank ^= 1;
    }
}

// ---------------------------------------------------------------------------
// MLP building blocks (identical arithmetic to R8-R12)
// ---------------------------------------------------------------------------
template <int CIN, int COUT, int PIN>
__device__ __forceinline__ void gemm_acc(const float* in_s,
                                         const float* __restrict__ W,
                                         const float* __restrict__ bias,
                                         float acc[4][COUT / 16],
                                         int c, int r) {
    constexpr int JW = COUT / 16;
#pragma unroll
    for (int j = 0; j < JW; ++j) {
        float bj = __ldg(bias + c * JW + j);
#pragma unroll
        for (int m = 0; m < 4; ++m) acc[m][j] = bj;
    }

    const float* wbase = W + c * JW;
    constexpr int CMAIN = CIN & ~3;

    for (int i = 0; i < CMAIN; i += 4) {
        float4 a0 = *(const float4*)(in_s + (r + 0)  * PIN + i);
        float4 a1 = *(const float4*)(in_s + (r + 8)  * PIN + i);
        float4 a2 = *(const float4*)(in_s + (r + 16) * PIN + i);
        float4 a3 = *(const float4*)(in_s + (r + 24) * PIN + i);
        const float av[4][4] = {
            {a0.x, a1.x, a2.x, a3.x},
            {a0.y, a1.y, a2.y, a3.y},
            {a0.z, a1.z, a2.z, a3.z},
            {a0.w, a1.w, a2.w, a3.w}};
#pragma unroll
        for (int u = 0; u < 4; ++u) {
            const float4* wp = (const float4*)(wbase + (i + u) * COUT);
#pragma unroll
            for (int v = 0; v < JW / 4; ++v) {
                float4 w = __ldg(wp + v);
#pragma unroll
                for (int m = 0; m < 4; ++m) {
                    acc[m][v * 4 + 0] = fmaf(av[u][m], w.x, acc[m][v * 4 + 0]);
                    acc[m][v * 4 + 1] = fmaf(av[u][m], w.y, acc[m][v * 4 + 1]);
                    acc[m][v * 4 + 2] = fmaf(av[u][m], w.z, acc[m][v * 4 + 2]);
                    acc[m][v * 4 + 3] = fmaf(av[u][m], w.w, acc[m][v * 4 + 3]);
                }
            }
        }
    }
    for (int i = CMAIN; i < CIN; ++i) {
        float s0 = in_s[(r + 0)  * PIN + i];
        float s1 = in_s[(r + 8)  * PIN + i];
        float s2 = in_s[(r + 16) * PIN + i];
        float s3 = in_s[(r + 24) * PIN + i];
        const float4* wp = (const float4*)(wbase + i * COUT);
#pragma unroll
        for (int v = 0; v < JW / 4; ++v) {
            float4 w = __ldg(wp + v);
#pragma unroll
            for (int q = 0; q < 4; ++q) {
                acc[0][v * 4 + q] = fmaf(s0, ((const float*)&w)[q], acc[0][v * 4 + q]);
                acc[1][v * 4 + q] = fmaf(s1, ((const float*)&w)[q], acc[1][v * 4 + q]);
                acc[2][v * 4 + q] = fmaf(s2, ((const float*)&w)[q], acc[2][v * 4 + q]);
                acc[3][v * 4 + q] = fmaf(s3, ((const float*)&w)[q], acc[3][v * 4 + q]);
            }
        }
    }
}

template <int COUT>
__device__ __forceinline__ void ln_relu_reg(float acc[4][COUT / 16],
                                            const float* __restrict__ g,
                                            const float* __restrict__ be, int c) {
    constexpr int JW = COUT / 16;
    float gv[JW], bv[JW];
#pragma unroll
    for (int j = 0; j < JW; ++j) { gv[j] = __ldg(g + c * JW + j); bv[j] = __ldg(be + c * JW + j); }
#pragma unroll
    for (int m = 0; m < 4; ++m) {
        float sum = 0.0f;
#pragma unroll
        for (int j = 0; j < JW; ++j) sum += acc[m][j];
        sum += __shfl_xor_sync(0xffffffffu, sum, 1);
        sum += __shfl_xor_sync(0xffffffffu, sum, 2);
        sum += __shfl_xor_sync(0xffffffffu, sum, 4);
        sum += __shfl_xor_sync(0xffffffffu, sum, 8);
        const float mu = sum * (1.0f / COUT);
        float sq = 0.0f;
#pragma unroll
        for (int j = 0; j < JW; ++j) { float d = acc[m][j] - mu; sq += d * d; }
        sq += __shfl_xor_sync(0xffffffffu, sq, 1);
        sq += __shfl_xor_sync(0xffffffffu, sq, 2);
        sq += __shfl_xor_sync(0xffffffffu, sq, 4);
        sq += __shfl_xor_sync(0xffffffffu, sq, 8);
        const float inv = rsqrtf(sq * (1.0f / COUT) + 1e-5f);
#pragma unroll
        for (int j = 0; j < JW; ++j)
            acc[m][j] = fmaxf((acc[m][j] - mu) * inv * gv[j] + bv[j], 0.0f);
    }
}

template <int COUT, int POUT>
__device__ __forceinline__ void store_rows(const float acc[4][COUT / 16],
                                           float* out_s, int c, int r) {
    constexpr int JW = COUT / 16;
#pragma unroll
    for (int m = 0; m < 4; ++m)
#pragma unroll
        for (int v = 0; v < JW / 4; ++v)
            *(float4*)(out_s + (r + 8 * m) * POUT + c * JW + v * 4) =
                make_float4(acc[m][v * 4 + 0], acc[m][v * 4 + 1],
                            acc[m][v * 4 + 2], acc[m][v * 4 + 3]);
}

// ---------------------------------------------------------------------------
// Worker role: NGRP groups of 128 threads, decoupled via named barriers.
// ---------------------------------------------------------------------------
__device__ void worker_role(const float* __restrict__ xyz,
                            const float* __restrict__ points,
                            const float* __restrict__ new_xyz,
                            const float* __restrict__ W1, const float* __restrict__ b1,
                            const float* __restrict__ g1, const float* __restrict__ be1,
                            const float* __restrict__ W2, const float* __restrict__ b2,
                            const float* __restrict__ g2, const float* __restrict__ be2,
                            const float* __restrict__ W3, const float* __restrict__ b3,
                            const float* __restrict__ g3, const float* __restrict__ be3,
                            float* __restrict__ new_points,
                            float* smem, int wb, int tid) {
    const int b = wb % BATCH;           // batch
    const int w = wb / BATCH;           // 0..NW_PER_B-1 worker index within batch
    const int grp  = tid >> 7;          // 0..NGRP-1
    const int gtid = tid & 127;
    const int c = gtid & 15;
    const int r = gtid >> 4;
    const int bid = grp + 1;            // named barrier id for this group

    float* sxyz = smem;                         // 12288 floats
    float* gbase = smem + SXYZ_F + grp * GRP_F;
    float* bufA  = gbase;                       // 32*68
    float* bufB  = gbase + 32 * PIN_A;          // 32*132
    int*   sIdx  = (int*)(smem + SXYZ_F + NGRP * GRP_F) + grp * 32;
    float* sCen  = (float*)((int*)(smem + SXYZ_F + NGRP * GRP_F) + NGRP * 32) + grp * 4;

    // stage batch xyz into smem (immutable input) — one block-wide barrier
    {
        const float4* src = (const float4*)(xyz + (size_t)b * NPTS * 3);
        for (int i = tid; i < SXYZ_F / 4; i += THREADS)
            ((float4*)sxyz)[i] = src[i];
    }
    __syncthreads();

    for (int base = w * NGRP; base < NPOINTS; base += NW_PER_B * NGRP) {
        const int s = base + grp;
        if (s >= NPOINTS) continue;     // uniform per group (128 threads)

        // ---- pace on producer: this group's centroid only ----
        if (gtid == 0) {
            while (ld_acquire(&g_progress[b * 32]) < s + 1) __nanosleep(100);
        }
        bar_grp(bid);

        // ---- ball query: warp 0 of the group ----
        if (gtid < 32) {
            const int lane = gtid;
            const float* cp = new_xyz + ((size_t)b * NPOINTS + s) * 3;
            const float cx = __ldcg(cp + 0);   // L2-only: line may be stale in L1
            const float cy = __ldcg(cp + 1);
            const float cz = __ldcg(cp + 2);
            if (lane < 3) sCen[lane] = __ldcg(cp + lane);
            const float R2 = (float)(0.2 * 0.2);
            int cnt = 0, first = -1;
            for (int rr = 0; rr < NPTS / 32; ++rr) {
                int n = rr * 32 + lane;
                float d = sqd_nofma(sxyz[n * 3], sxyz[n * 3 + 1], sxyz[n * 3 + 2],
                                    cx, cy, cz);
                bool ok = !(d > R2);
                unsigned m = __ballot_sync(0xffffffffu, ok);
                if (first < 0 && m) first = rr * 32 + (__ffs(m) - 1);
                if (ok) {
                    int pos = cnt + __popc(m & ((1u << lane) - 1u));
                    if (pos < NSAMPLE) sIdx[pos] = n;
                }
                cnt += __popc(m);
                if (cnt >= NSAMPLE) break;
            }
            if (cnt < NSAMPLE && lane >= cnt && lane < NSAMPLE) sIdx[lane] = first;
        }
        bar_grp(bid);

        // ---- gather: 4 threads per sample ----
        {
            const int k = gtid >> 2, q = gtid & 3;
            const int n = sIdx[k];
            const float4* prow = (const float4*)(points + ((size_t)b * NPTS + n) * 64) + q * 4;
            float* dst = bufA + k * PIN_A + 3 + q * 16;
#pragma unroll
            for (int v = 0; v < 4; ++v) {
                float4 f = __ldg(prow + v);
                dst[v * 4 + 0] = f.x;
                dst[v * 4 + 1] = f.y;
                dst[v * 4 + 2] = f.z;
                dst[v * 4 + 3] = f.w;
            }
            if (q == 0) {
                bufA[k * PIN_A + 0] = sxyz[n * 3 + 0] - sCen[0];
                bufA[k * PIN_A + 1] = sxyz[n * 3 + 1] - sCen[1];
                bufA[k * PIN_A + 2] = sxyz[n * 3 + 2] - sCen[2];
            }
        }
        bar_grp(bid);

        {   // layer 1: 67 -> 64
            float acc[4][4];
            gemm_acc<67, 64, PIN_A>(bufA, W1, b1, acc, c, r);
            ln_relu_reg<64>(acc, g1, be1, c);
            store_rows<64, PIN_B>(acc, bufB, c, r);
        }
        bar_grp(bid);

        {   // layer 2: 64 -> 64
            float acc[4][4];
            gemm_acc<64, 64, PIN_B>(bufB, W2, b2, acc, c, r);
            ln_relu_reg<64>(acc, g2, be2, c);
            store_rows<64, PIN_A>(acc, bufA, c, r);
        }
        bar_grp(bid);

        {   // layer 3: 64 -> 128, fused partial max over 4 samples
            float acc[4][8];
            gemm_acc<64, 128, PIN_A>(bufA, W3, b3, acc, c, r);
            ln_relu_reg<128>(acc, g3, be3, c);
#pragma unroll
            for (int j = 0; j < 8; ++j) {
                float pm = fmaxf(fmaxf(acc[0][j], acc[1][j]), fmaxf(acc[2][j], acc[3][j]));
                bufB[r * PIN_B + c * 8 + j] = pm;
            }
        }
        bar_grp(bid);

        {   // final max over 8 r-partials; relu >= 0 so init 0 exact
            float m = 0.0f;
#pragma unroll
            for (int k = 0; k < 8; ++k) m = fmaxf(m, bufB[k * PIN_B + gtid]);
            new_points[((size_t)b * NPOINTS + s) * 128 + gtid] = m;
        }
        bar_grp(bid);   // protect bufs before next iteration's gather
    }
}

// ---------------------------------------------------------------------------
__global__ __launch_bounds__(THREADS, 1) void fused_kernel(
    const float* __restrict__ xyz, const float* __restrict__ points,
    const float* __restrict__ W1, const float* __restrict__ b1,
    const float* __restrict__ g1, const float* __restrict__ be1,
    const float* __restrict__ W2, const float* __restrict__ b2,
    const float* __restrict__ g2, const float* __restrict__ be2,
    const float* __restrict__ W3, const float* __restrict__ b3,
    const float* __restrict__ g3, const float* __restrict__ be3,
    float* __restrict__ new_xyz, float* __restrict__ new_points) {
    extern __shared__ float smem[];
    const int tid = threadIdx.x;
    if (blockIdx.x < BATCH) {
        fps_role(xyz, new_xyz, blockIdx.x, tid);
    } else {
        worker_role(xyz, points, new_xyz,
                    W1, b1, g1, be1, W2, b2, g2, be2, W3, b3, g3, be3,
                    new_points, smem, blockIdx.x - BATCH, tid);
    }
}

// ---------------------------------------------------------------------------
extern "C" void kernel_launch(void* const* d_in, const int* in_sizes, int n_in,
                              void* d_out, int out_size) {
    (void)in_sizes; (void)n_in; (void)out_size;
    const float* xyz    = (const float*)d_in[0];
    const float* points = (const float*)d_in[1];
    const float* W1  = (const float*)d_in[2];
    const float* b1  = (const float*)d_in[3];
    const float* g1  = (const float*)d_in[4];
    const float* be1 = (const float*)d_in[5];
    const float* W2  = (const float*)d_in[6];
    const float* b2  = (const float*)d_in[7];
    const float* g2  = (const float*)d_in[8];
    const float* be2 = (const float*)d_in[9];
    const float* W3  = (const float*)d_in[10];
    const float* b3  = (const float*)d_in[11];
    const float* g3  = (const float*)d_in[12];
    const float* be3 = (const float*)d_in[13];

    float* out        = (float*)d_out;
    float* new_xyz    = out;                          // [8,1024,3]
    float* new_points = out + BATCH * NPOINTS * 3;    // [8,1024,128]

    cudaFuncSetAttribute(fused_kernel, cudaFuncAttributeMaxDynamicSharedMemorySize,
                         SMEM_DYN);

    reset_kernel<<<1, 256>>>();
    fused_kernel<<<NBLOCKS, THREADS, SMEM_DYN>>>(xyz, points,
                                                 W1, b1, g1, be1,
                                                 W2, b2, g2, be2,
                                                 W3, b3, g3, be3,
                                                 new_xyz, new_points);
}

// round 14
// speedup vs baseline: 2.1559x; 1.0387x over previous
#include <cuda_runtime.h>

#define BATCH   8
#define NPTS    4096
#define NPOINTS 1024
#define NSAMPLE 32
#define PIN_A   68
#define PIN_B   132
#define NW_PER_B 17                    // worker blocks per batch
#define NWORKERS (NW_PER_B * BATCH)    // 136
#define NBLOCKS  (BATCH + NWORKERS)    // 144 <= 148 SMs -> all resident wave 1
#define NGRP     4
#define THREADS  512

#define SXYZ_F   (NPTS * 3)                    // 12288 floats
#define GRP_F    (32 * PIN_A + 32 * PIN_B)     // 6400 floats per group
#define SMEM_DYN ((SXYZ_F + NGRP * GRP_F) * 4 + NGRP * 32 * 4 + NGRP * 4 * 4)

// packed centroid+flag: {x, y, z, bits(t+1)}. One 16B STG publishes both the
// payload and the flag (single-sector write -> no tearing, no fences needed).
__device__ float4 g_cent[BATCH * NPOINTS];

// ---------------------------------------------------------------------------
__device__ __forceinline__ float sqd_nofma(float x, float y, float z,
                                           float cx, float cy, float cz) {
    float dx = x - cx, dy = y - cy, dz = z - cz;
    return __fadd_rn(__fadd_rn(__fmul_rn(dx, dx), __fmul_rn(dy, dy)), __fmul_rn(dz, dz));
}

__device__ __forceinline__ unsigned long long f2_add(unsigned long long a, unsigned long long b) {
    unsigned long long r;
    asm("add.rn.f32x2 %0, %1, %2;" : "=l"(r) : "l"(a), "l"(b));
    return r;
}
__device__ __forceinline__ unsigned long long f2_mul(unsigned long long a, unsigned long long b) {
    unsigned long long r;
    asm("mul.rn.f32x2 %0, %1, %2;" : "=l"(r) : "l"(a), "l"(b));
    return r;
}
__device__ __forceinline__ unsigned long long f2_pack(float lo, float hi) {
    unsigned long long r;
    asm("mov.b64 %0, {%1, %2};" : "=l"(r) : "f"(lo), "f"(hi));
    return r;
}
__device__ __forceinline__ void f2_unpack(unsigned long long v, float& lo, float& hi) {
    asm("mov.b64 {%0, %1}, %2;" : "=f"(lo), "=f"(hi) : "l"(v));
}

__device__ __forceinline__ float4 ldcg_v4(const float4* p) {
    float4 v;
    asm volatile("ld.global.cg.v4.f32 {%0,%1,%2,%3}, [%4];"
                 : "=f"(v.x), "=f"(v.y), "=f"(v.z), "=f"(v.w) : "l"(p) : "memory");
    return v;
}
__device__ __forceinline__ void stcg_v4(float4* p, float x, float y, float z, float w) {
    asm volatile("st.global.cg.v4.f32 [%0], {%1,%2,%3,%4};"
                 :: "l"(p), "f"(x), "f"(y), "f"(z), "f"(w) : "memory");
}

// 128-thread named barrier for group decoupling (ids 1..NGRP)
__device__ __forceinline__ void bar_grp(int id) {
    asm volatile("bar.sync %0, 128;" :: "r"(id) : "memory");
}

// ---------------------------------------------------------------------------
__global__ void reset_kernel() {
    int i = blockIdx.x * 1024 + threadIdx.x;
    if (i < BATCH * NPOINTS) g_cent[i] = make_float4(0.f, 0.f, 0.f, 0.f);
}

// ---------------------------------------------------------------------------
// FPS role (blocks 0..7): identical selection math to R7-R13. tid0 publishes
// each centroid as one packed 16B {x,y,z,flag} store — no fences, and the
// publish is off the critical path (all threads compute idx themselves).
// ---------------------------------------------------------------------------
__device__ void fps_role(const float* __restrict__ xyz, float* __restrict__ new_xyz,
                         int b, int tid) {
    const int lane = tid & 31;
    const float* base = xyz + (size_t)b * NPTS * 3;

    unsigned long long pxp[4], pyp[4], pzp[4];
    float pd[8];
#pragma unroll
    for (int p = 0; p < 4; ++p) {
        int n0 = tid + p * 512;
        int n1 = n0 + 2048;
        pxp[p] = f2_pack(base[n0 * 3 + 0], base[n1 * 3 + 0]);
        pyp[p] = f2_pack(base[n0 * 3 + 1], base[n1 * 3 + 1]);
        pzp[p] = f2_pack(base[n0 * 3 + 2], base[n1 * 3 + 2]);
        pd[p] = 1e10f; pd[p + 4] = 1e10f;
    }

    __shared__ uint2 sWarp[32];   // ping-pong banks of 16

    float cx = __ldg(base + 0), cy = __ldg(base + 1), cz = __ldg(base + 2);
    if (tid == 0) {
        float* o = new_xyz + (size_t)b * NPOINTS * 3;
        o[0] = cx; o[1] = cy; o[2] = cz;
        stcg_v4(&g_cent[b * NPOINTS + 0], cx, cy, cz, __int_as_float(1));
    }

    int bank = 0;
    for (int t = 1; t < NPOINTS; ++t) {
        const unsigned long long ncx2 = f2_pack(-cx, -cx);
        const unsigned long long ncy2 = f2_pack(-cy, -cy);
        const unsigned long long ncz2 = f2_pack(-cz, -cz);
#pragma unroll
        for (int p = 0; p < 4; ++p) {
            unsigned long long dx = f2_add(pxp[p], ncx2);
            unsigned long long dy = f2_add(pyp[p], ncy2);
            unsigned long long dz = f2_add(pzp[p], ncz2);
            unsigned long long s  = f2_add(f2_add(f2_mul(dx, dx), f2_mul(dy, dy)),
                                           f2_mul(dz, dz));
            float lo, hi;
            f2_unpack(s, lo, hi);
            pd[p]     = fminf(pd[p],     lo);
            pd[p + 4] = fminf(pd[p + 4], hi);
        }

        float m0 = fmaxf(pd[0], pd[1]);
        float m1 = fmaxf(pd[2], pd[3]);
        float m2 = fmaxf(pd[4], pd[5]);
        float m3 = fmaxf(pd[6], pd[7]);
        const float bd = fmaxf(fmaxf(m0, m1), fmaxf(m2, m3));

        int bi = 0x7fffffff;
#pragma unroll
        for (int p = 0; p < 4; ++p)
            bi = min(bi, (pd[p] == bd) ? (tid + p * 512) : 0x7fffffff);
#pragma unroll
        for (int p = 0; p < 4; ++p)
            bi = min(bi, (pd[p + 4] == bd) ? (tid + p * 512 + 2048) : 0x7fffffff);

        const unsigned bdb = __float_as_uint(bd);
        const unsigned wd  = __reduce_max_sync(0xffffffffu, bdb);
        const unsigned wi  = __reduce_min_sync(0xffffffffu,
                                (bdb == wd) ? (unsigned)bi : 0xffffffffu);
        if (lane == 0) sWarp[bank * 16 + (tid >> 5)] = make_uint2(wd, wi);
        __syncthreads();

        const uint2 k  = sWarp[bank * 16 + (lane & 15)];
        const unsigned gd = __reduce_max_sync(0xffffffffu, k.x);
        const unsigned gi = __reduce_min_sync(0xffffffffu,
                                (k.x == gd) ? k.y : 0xffffffffu);
        const int idx = (int)gi;
        cx = __ldg(base + idx * 3 + 0);
        cy = __ldg(base + idx * 3 + 1);
        cz = __ldg(base + idx * 3 + 2);
        if (tid == 0) {
            float* o = new_xyz + ((size_t)b * NPOINTS + t) * 3;
            o[0] = cx; o[1] = cy; o[2] = cz;
            stcg_v4(&g_cent[b * NPOINTS + t], cx, cy, cz, __int_as_float(t + 1));
        }
        bank ^= 1;
    }
}

// ---------------------------------------------------------------------------
// MLP building blocks (identical arithmetic to R8-R13)
// ---------------------------------------------------------------------------
template <int CIN, int COUT, int PIN>
__device__ __forceinline__ void gemm_acc(const float* in_s,
                                         const float* __restrict__ W,
                                         const float* __restrict__ bias,
                                         float acc[4][COUT / 16],
                                         int c, int r) {
    constexpr int JW = COUT / 16;
#pragma unroll
    for (int j = 0; j < JW; ++j) {
        float bj = __ldg(bias + c * JW + j);
#pragma unroll
        for (int m = 0; m < 4; ++m) acc[m][j] = bj;
    }

    const float* wbase = W + c * JW;
    constexpr int CMAIN = CIN & ~3;

    for (int i = 0; i < CMAIN; i += 4) {
        float4 a0 = *(const float4*)(in_s + (r + 0)  * PIN + i);
        float4 a1 = *(const float4*)(in_s + (r + 8)  * PIN + i);
        float4 a2 = *(const float4*)(in_s + (r + 16) * PIN + i);
        float4 a3 = *(const float4*)(in_s + (r + 24) * PIN + i);
        const float av[4][4] = {
            {a0.x, a1.x, a2.x, a3.x},
            {a0.y, a1.y, a2.y, a3.y},
            {a0.z, a1.z, a2.z, a3.z},
            {a0.w, a1.w, a2.w, a3.w}};
#pragma unroll
        for (int u = 0; u < 4; ++u) {
            const float4* wp = (const float4*)(wbase + (i + u) * COUT);
#pragma unroll
            for (int v = 0; v < JW / 4; ++v) {
                float4 w = __ldg(wp + v);
#pragma unroll
                for (int m = 0; m < 4; ++m) {
                    acc[m][v * 4 + 0] = fmaf(av[u][m], w.x, acc[m][v * 4 + 0]);
                    acc[m][v * 4 + 1] = fmaf(av[u][m], w.y, acc[m][v * 4 + 1]);
                    acc[m][v * 4 + 2] = fmaf(av[u][m], w.z, acc[m][v * 4 + 2]);
                    acc[m][v * 4 + 3] = fmaf(av[u][m], w.w, acc[m][v * 4 + 3]);
                }
            }
        }
    }
    for (int i = CMAIN; i < CIN; ++i) {
        float s0 = in_s[(r + 0)  * PIN + i];
        float s1 = in_s[(r + 8)  * PIN + i];
        float s2 = in_s[(r + 16) * PIN + i];
        float s3 = in_s[(r + 24) * PIN + i];
        const float4* wp = (const float4*)(wbase + i * COUT);
#pragma unroll
        for (int v = 0; v < JW / 4; ++v) {
            float4 w = __ldg(wp + v);
#pragma unroll
            for (int q = 0; q < 4; ++q) {
                acc[0][v * 4 + q] = fmaf(s0, ((const float*)&w)[q], acc[0][v * 4 + q]);
                acc[1][v * 4 + q] = fmaf(s1, ((const float*)&w)[q], acc[1][v * 4 + q]);
                acc[2][v * 4 + q] = fmaf(s2, ((const float*)&w)[q], acc[2][v * 4 + q]);
                acc[3][v * 4 + q] = fmaf(s3, ((const float*)&w)[q], acc[3][v * 4 + q]);
            }
        }
    }
}

template <int COUT>
__device__ __forceinline__ void ln_relu_reg(float acc[4][COUT / 16],
                                            const float* __restrict__ g,
                                            const float* __restrict__ be, int c) {
    constexpr int JW = COUT / 16;
    float gv[JW], bv[JW];
#pragma unroll
    for (int j = 0; j < JW; ++j) { gv[j] = __ldg(g + c * JW + j); bv[j] = __ldg(be + c * JW + j); }
#pragma unroll
    for (int m = 0; m < 4; ++m) {
        float sum = 0.0f;
#pragma unroll
        for (int j = 0; j < JW; ++j) sum += acc[m][j];
        sum += __shfl_xor_sync(0xffffffffu, sum, 1);
        sum += __shfl_xor_sync(0xffffffffu, sum, 2);
        sum += __shfl_xor_sync(0xffffffffu, sum, 4);
        sum += __shfl_xor_sync(0xffffffffu, sum, 8);
        const float mu = sum * (1.0f / COUT);
        float sq = 0.0f;
#pragma unroll
        for (int j = 0; j < JW; ++j) { float d = acc[m][j] - mu; sq += d * d; }
        sq += __shfl_xor_sync(0xffffffffu, sq, 1);
        sq += __shfl_xor_sync(0xffffffffu, sq, 2);
        sq += __shfl_xor_sync(0xffffffffu, sq, 4);
        sq += __shfl_xor_sync(0xffffffffu, sq, 8);
        const float inv = rsqrtf(sq * (1.0f / COUT) + 1e-5f);
#pragma unroll
        for (int j = 0; j < JW; ++j)
            acc[m][j] = fmaxf((acc[m][j] - mu) * inv * gv[j] + bv[j], 0.0f);
    }
}

template <int COUT, int POUT>
__device__ __forceinline__ void store_rows(const float acc[4][COUT / 16],
                                           float* out_s, int c, int r) {
    constexpr int JW = COUT / 16;
#pragma unroll
    for (int m = 0; m < 4; ++m)
#pragma unroll
        for (int v = 0; v < JW / 4; ++v)
            *(float4*)(out_s + (r + 8 * m) * POUT + c * JW + v * 4) =
                make_float4(acc[m][v * 4 + 0], acc[m][v * 4 + 1],
                            acc[m][v * 4 + 2], acc[m][v * 4 + 3]);
}

// ---------------------------------------------------------------------------
// Worker role: NGRP groups of 128 threads, decoupled via named barriers.
// Pacing = one fence-free packed poll on g_cent[b][s].
// ---------------------------------------------------------------------------
__device__ void worker_role(const float* __restrict__ xyz,
                            const float* __restrict__ points,
                            const float* __restrict__ W1, const float* __restrict__ b1,
                            const float* __restrict__ g1, const float* __restrict__ be1,
                            const float* __restrict__ W2, const float* __restrict__ b2,
                            const float* __restrict__ g2, const float* __restrict__ be2,
                            const float* __restrict__ W3, const float* __restrict__ b3,
                            const float* __restrict__ g3, const float* __restrict__ be3,
                            float* __restrict__ new_points,
                            float* smem, int wb, int tid) {
    const int b = wb % BATCH;           // batch
    const int w = wb / BATCH;           // 0..NW_PER_B-1 worker index within batch
    const int grp  = tid >> 7;          // 0..NGRP-1
    const int gtid = tid & 127;
    const int c = gtid & 15;
    const int r = gtid >> 4;
    const int bid = grp + 1;            // named barrier id for this group

    float* sxyz = smem;                         // 12288 floats
    float* gbase = smem + SXYZ_F + grp * GRP_F;
    float* bufA  = gbase;                       // 32*68
    float* bufB  = gbase + 32 * PIN_A;          // 32*132
    int*   sIdx  = (int*)(smem + SXYZ_F + NGRP * GRP_F) + grp * 32;
    float* sCen  = (float*)((int*)(smem + SXYZ_F + NGRP * GRP_F) + NGRP * 32) + grp * 4;

    // stage batch xyz into smem (immutable input) — one block-wide barrier
    {
        const float4* src = (const float4*)(xyz + (size_t)b * NPTS * 3);
        for (int i = tid; i < SXYZ_F / 4; i += THREADS)
            ((float4*)sxyz)[i] = src[i];
    }
    __syncthreads();

    for (int base = w * NGRP; base < NPOINTS; base += NW_PER_B * NGRP) {
        const int s = base + grp;

        // ---- pace on producer: packed centroid+flag, no fences ----
        if (gtid == 0) {
            const float4* cp = &g_cent[b * NPOINTS + s];
            float4 cen = ldcg_v4(cp);
            while (__float_as_int(cen.w) != s + 1) {
                __nanosleep(80);
                cen = ldcg_v4(cp);
            }
            sCen[0] = cen.x; sCen[1] = cen.y; sCen[2] = cen.z;
        }
        bar_grp(bid);

        // ---- ball query: warp 0 of the group ----
        if (gtid < 32) {
            const int lane = gtid;
            const float cx = sCen[0], cy = sCen[1], cz = sCen[2];
            const float R2 = (float)(0.2 * 0.2);
            int cnt = 0, first = -1;
            for (int rr = 0; rr < NPTS / 32; ++rr) {
                int n = rr * 32 + lane;
                float d = sqd_nofma(sxyz[n * 3], sxyz[n * 3 + 1], sxyz[n * 3 + 2],
                                    cx, cy, cz);
                bool ok = !(d > R2);
                unsigned m = __ballot_sync(0xffffffffu, ok);
                if (first < 0 && m) first = rr * 32 + (__ffs(m) - 1);
                if (ok) {
                    int pos = cnt + __popc(m & ((1u << lane) - 1u));
                    if (pos < NSAMPLE) sIdx[pos] = n;
                }
                cnt += __popc(m);
                if (cnt >= NSAMPLE) break;
            }
            if (cnt < NSAMPLE && lane >= cnt && lane < NSAMPLE) sIdx[lane] = first;
        }
        bar_grp(bid);

        // ---- gather: 4 threads per sample ----
        {
            const int k = gtid >> 2, q = gtid & 3;
            const int n = sIdx[k];
            const float4* prow = (const float4*)(points + ((size_t)b * NPTS + n) * 64) + q * 4;
            float* dst = bufA + k * PIN_A + 3 + q * 16;
#pragma unroll
            for (int v = 0; v < 4; ++v) {
                float4 f = __ldg(prow + v);
                dst[v * 4 + 0] = f.x;
                dst[v * 4 + 1] = f.y;
                dst[v * 4 + 2] = f.z;
                dst[v * 4 + 3] = f.w;
            }
            if (q == 0) {
                bufA[k * PIN_A + 0] = sxyz[n * 3 + 0] - sCen[0];
                bufA[k * PIN_A + 1] = sxyz[n * 3 + 1] - sCen[1];
                bufA[k * PIN_A + 2] = sxyz[n * 3 + 2] - sCen[2];
            }
        }
        bar_grp(bid);

        {   // layer 1: 67 -> 64
            float acc[4][4];
            gemm_acc<67, 64, PIN_A>(bufA, W1, b1, acc, c, r);
            ln_relu_reg<64>(acc, g1, be1, c);
            store_rows<64, PIN_B>(acc, bufB, c, r);
        }
        bar_grp(bid);

        {   // layer 2: 64 -> 64
            float acc[4][4];
            gemm_acc<64, 64, PIN_B>(bufB, W2, b2, acc, c, r);
            ln_relu_reg<64>(acc, g2, be2, c);
            store_rows<64, PIN_A>(acc, bufA, c, r);
        }
        bar_grp(bid);

        {   // layer 3: 64 -> 128, fused partial max over 4 samples
            float acc[4][8];
            gemm_acc<64, 128, PIN_A>(bufA, W3, b3, acc, c, r);
            ln_relu_reg<128>(acc, g3, be3, c);
#pragma unroll
            for (int j = 0; j < 8; ++j) {
                float pm = fmaxf(fmaxf(acc[0][j], acc[1][j]), fmaxf(acc[2][j], acc[3][j]));
                bufB[r * PIN_B + c * 8 + j] = pm;
            }
        }
        bar_grp(bid);

        {   // final max over 8 r-partials; relu >= 0 so init 0 exact
            float m = 0.0f;
#pragma unroll
            for (int k = 0; k < 8; ++k) m = fmaxf(m, bufB[k * PIN_B + gtid]);
            new_points[((size_t)b * NPOINTS + s) * 128 + gtid] = m;
        }
        bar_grp(bid);   // protect bufs before next iteration's gather
    }
}

// ---------------------------------------------------------------------------
__global__ __launch_bounds__(THREADS, 1) void fused_kernel(
    const float* __restrict__ xyz, const float* __restrict__ points,
    const float* __restrict__ W1, const float* __restrict__ b1,
    const float* __restrict__ g1, const float* __restrict__ be1,
    const float* __restrict__ W2, const float* __restrict__ b2,
    const float* __restrict__ g2, const float* __restrict__ be2,
    const float* __restrict__ W3, const float* __restrict__ b3,
    const float* __restrict__ g3, const float* __restrict__ be3,
    float* __restrict__ new_xyz, float* __restrict__ new_points) {
    extern __shared__ float smem[];
    const int tid = threadIdx.x;
    if (blockIdx.x < BATCH) {
        fps_role(xyz, new_xyz, blockIdx.x, tid);
    } else {
        worker_role(xyz, points,
                    W1, b1, g1, be1, W2, b2, g2, be2, W3, b3, g3, be3,
                    new_points, smem, blockIdx.x - BATCH, tid);
    }
}

// ---------------------------------------------------------------------------
extern "C" void kernel_launch(void* const* d_in, const int* in_sizes, int n_in,
                              void* d_out, int out_size) {
    (void)in_sizes; (void)n_in; (void)out_size;
    const float* xyz    = (const float*)d_in[0];
    const float* points = (const float*)d_in[1];
    const float* W1  = (const float*)d_in[2];
    const float* b1  = (const float*)d_in[3];
    const float* g1  = (const float*)d_in[4];
    const float* be1 = (const float*)d_in[5];
    const float* W2  = (const float*)d_in[6];
    const float* b2  = (const float*)d_in[7];
    const float* g2  = (const float*)d_in[8];
    const float* be2 = (const float*)d_in[9];
    const float* W3  = (const float*)d_in[10];
    const float* b3  = (const float*)d_in[11];
    const float* g3  = (const float*)d_in[12];
    const float* be3 = (const float*)d_in[13];

    float* out        = (float*)d_out;
    float* new_xyz    = out;                          // [8,1024,3]
    float* new_points = out + BATCH * NPOINTS * 3;    // [8,1024,128]

    cudaFuncSetAttribute(fused_kernel, cudaFuncAttributeMaxDynamicSharedMemorySize,
                         SMEM_DYN);

    reset_kernel<<<BATCH, 1024>>>();
    fused_kernel<<<NBLOCKS, THREADS, SMEM_DYN>>>(xyz, points,
                                                 W1, b1, g1, be1,
                                                 W2, b2, g2, be2,
                                                 W3, b3, g3, be3,
                                                 new_xyz, new_points);
}

// round 15
// speedup vs baseline: 2.1733x; 1.0081x over previous
#include <cuda_runtime.h>

#define BATCH   8
#define NPTS    4096
#define NPOINTS 1024
#define NSAMPLE 32
#define PIN_A   68
#define PIN_B   132
#define NW_PER_B 17                    // worker blocks per batch
#define NWORKERS (NW_PER_B * BATCH)    // 136
#define NBLOCKS  (BATCH + NWORKERS)    // 144 <= 148 SMs -> all resident wave 1
#define NGRP     4
#define THREADS  512

#define SXYZ_F   (NPTS * 3)                    // 12288 floats
#define GRP_F    (32 * PIN_A + 32 * PIN_B)     // 6400 floats per group
#define SMEM_DYN ((SXYZ_F + NGRP * GRP_F) * 4 + NGRP * 32 * 4 + NGRP * 4 * 4)

// packed centroid+flag: {x, y, z, bits(t+1)}. One 16B STG publishes both the
// payload and the flag (single-sector write -> no tearing, no fences needed).
__device__ float4 g_cent[BATCH * NPOINTS];

// ---------------------------------------------------------------------------
__device__ __forceinline__ float sqd_nofma(float x, float y, float z,
                                           float cx, float cy, float cz) {
    float dx = x - cx, dy = y - cy, dz = z - cz;
    return __fadd_rn(__fadd_rn(__fmul_rn(dx, dx), __fmul_rn(dy, dy)), __fmul_rn(dz, dz));
}

__device__ __forceinline__ unsigned long long f2_add(unsigned long long a, unsigned long long b) {
    unsigned long long r;
    asm("add.rn.f32x2 %0, %1, %2;" : "=l"(r) : "l"(a), "l"(b));
    return r;
}
__device__ __forceinline__ unsigned long long f2_mul(unsigned long long a, unsigned long long b) {
    unsigned long long r;
    asm("mul.rn.f32x2 %0, %1, %2;" : "=l"(r) : "l"(a), "l"(b));
    return r;
}
__device__ __forceinline__ unsigned long long f2_pack(float lo, float hi) {
    unsigned long long r;
    asm("mov.b64 %0, {%1, %2};" : "=l"(r) : "f"(lo), "f"(hi));
    return r;
}
__device__ __forceinline__ void f2_unpack(unsigned long long v, float& lo, float& hi) {
    asm("mov.b64 {%0, %1}, %2;" : "=f"(lo), "=f"(hi) : "l"(v));
}

__device__ __forceinline__ float4 ldcg_v4(const float4* p) {
    float4 v;
    asm volatile("ld.global.cg.v4.f32 {%0,%1,%2,%3}, [%4];"
                 : "=f"(v.x), "=f"(v.y), "=f"(v.z), "=f"(v.w) : "l"(p) : "memory");
    return v;
}
__device__ __forceinline__ void stcg_v4(float4* p, float x, float y, float z, float w) {
    asm volatile("st.global.cg.v4.f32 [%0], {%1,%2,%3,%4};"
                 :: "l"(p), "f"(x), "f"(y), "f"(z), "f"(w) : "memory");
}

// 128-thread named barrier for group decoupling (ids 1..NGRP)
__device__ __forceinline__ void bar_grp(int id) {
    asm volatile("bar.sync %0, 128;" :: "r"(id) : "memory");
}

// ---------------------------------------------------------------------------
__global__ void reset_kernel() {
    int i = blockIdx.x * 1024 + threadIdx.x;
    if (i < BATCH * NPOINTS) g_cent[i] = make_float4(0.f, 0.f, 0.f, 0.f);
}

// ---------------------------------------------------------------------------
// FPS role (blocks 0..7): selection math bit-identical to R7-R14.
//  - points stored PRE-NEGATED: dx = (-p) + c = -(p-c); squares identical.
//  - per-step publish by tid 32 (one packed 16B st.cg; all threads know cx/cy/cz)
//  - new_xyz written ONCE after the loop from g_cent (off the serial path)
// ---------------------------------------------------------------------------
__device__ void fps_role(const float* __restrict__ xyz, float* __restrict__ new_xyz,
                         int b, int tid) {
    const int lane = tid & 31;
    const float* base = xyz + (size_t)b * NPTS * 3;

    unsigned long long pxp[4], pyp[4], pzp[4];   // negated coords, packed pairs
    float pd[8];
#pragma unroll
    for (int p = 0; p < 4; ++p) {
        int n0 = tid + p * 512;
        int n1 = n0 + 2048;
        pxp[p] = f2_pack(-base[n0 * 3 + 0], -base[n1 * 3 + 0]);
        pyp[p] = f2_pack(-base[n0 * 3 + 1], -base[n1 * 3 + 1]);
        pzp[p] = f2_pack(-base[n0 * 3 + 2], -base[n1 * 3 + 2]);
        pd[p] = 1e10f; pd[p + 4] = 1e10f;
    }

    __shared__ uint2 sWarp[32];   // ping-pong banks of 16

    float cx = __ldg(base + 0), cy = __ldg(base + 1), cz = __ldg(base + 2);
    if (tid == 0)
        stcg_v4(&g_cent[b * NPOINTS + 0], cx, cy, cz, __int_as_float(1));

    int bank = 0;
    for (int t = 1; t < NPOINTS; ++t) {
        const unsigned long long cx2 = f2_pack(cx, cx);
        const unsigned long long cy2 = f2_pack(cy, cy);
        const unsigned long long cz2 = f2_pack(cz, cz);
#pragma unroll
        for (int p = 0; p < 4; ++p) {
            unsigned long long dx = f2_add(pxp[p], cx2);   // -(p-c): square equal
            unsigned long long dy = f2_add(pyp[p], cy2);
            unsigned long long dz = f2_add(pzp[p], cz2);
            unsigned long long s  = f2_add(f2_add(f2_mul(dx, dx), f2_mul(dy, dy)),
                                           f2_mul(dz, dz));
            float lo, hi;
            f2_unpack(s, lo, hi);
            pd[p]     = fminf(pd[p],     lo);
            pd[p + 4] = fminf(pd[p + 4], hi);
        }

        float m0 = fmaxf(pd[0], pd[1]);
        float m1 = fmaxf(pd[2], pd[3]);
        float m2 = fmaxf(pd[4], pd[5]);
        float m3 = fmaxf(pd[6], pd[7]);
        const float bd = fmaxf(fmaxf(m0, m1), fmaxf(m2, m3));

        int bi = 0x7fffffff;
#pragma unroll
        for (int p = 0; p < 4; ++p)
            bi = min(bi, (pd[p] == bd) ? (tid + p * 512) : 0x7fffffff);
#pragma unroll
        for (int p = 0; p < 4; ++p)
            bi = min(bi, (pd[p + 4] == bd) ? (tid + p * 512 + 2048) : 0x7fffffff);

        const unsigned bdb = __float_as_uint(bd);
        const unsigned wd  = __reduce_max_sync(0xffffffffu, bdb);
        const unsigned wi  = __reduce_min_sync(0xffffffffu,
                                (bdb == wd) ? (unsigned)bi : 0xffffffffu);
        if (lane == 0) sWarp[bank * 16 + (tid >> 5)] = make_uint2(wd, wi);
        __syncthreads();

        const uint2 k  = sWarp[bank * 16 + (lane & 15)];
        const unsigned gd = __reduce_max_sync(0xffffffffu, k.x);
        const unsigned gi = __reduce_min_sync(0xffffffffu,
                                (k.x == gd) ? k.y : 0xffffffffu);
        const int idx = (int)gi;
        cx = __ldg(base + idx * 3 + 0);
        cy = __ldg(base + idx * 3 + 1);
        cz = __ldg(base + idx * 3 + 2);
        if (tid == 32)     // warp 1 publishes; no thread does double duty
            stcg_v4(&g_cent[b * NPOINTS + t], cx, cy, cz, __int_as_float(t + 1));
        bank ^= 1;
    }

    // final: materialize new_xyz from g_cent (once, off the serial path)
    for (int i = tid; i < NPOINTS; i += THREADS) {
        float4 cen = ldcg_v4(&g_cent[b * NPOINTS + i]);
        float* o = new_xyz + ((size_t)b * NPOINTS + i) * 3;
        o[0] = cen.x; o[1] = cen.y; o[2] = cen.z;
    }
}

// ---------------------------------------------------------------------------
// MLP building blocks (identical arithmetic to R8-R14)
// ---------------------------------------------------------------------------
template <int CIN, int COUT, int PIN>
__device__ __forceinline__ void gemm_acc(const float* in_s,
                                         const float* __restrict__ W,
                                         const float* __restrict__ bias,
                                         float acc[4][COUT / 16],
                                         int c, int r) {
    constexpr int JW = COUT / 16;
#pragma unroll
    for (int j = 0; j < JW; ++j) {
        float bj = __ldg(bias + c * JW + j);
#pragma unroll
        for (int m = 0; m < 4; ++m) acc[m][j] = bj;
    }

    const float* wbase = W + c * JW;
    constexpr int CMAIN = CIN & ~3;

    for (int i = 0; i < CMAIN; i += 4) {
        float4 a0 = *(const float4*)(in_s + (r + 0)  * PIN + i);
        float4 a1 = *(const float4*)(in_s + (r + 8)  * PIN + i);
        float4 a2 = *(const float4*)(in_s + (r + 16) * PIN + i);
        float4 a3 = *(const float4*)(in_s + (r + 24) * PIN + i);
        const float av[4][4] = {
            {a0.x, a1.x, a2.x, a3.x},
            {a0.y, a1.y, a2.y, a3.y},
            {a0.z, a1.z, a2.z, a3.z},
            {a0.w, a1.w, a2.w, a3.w}};
#pragma unroll
        for (int u = 0; u < 4; ++u) {
            const float4* wp = (const float4*)(wbase + (i + u) * COUT);
#pragma unroll
            for (int v = 0; v < JW / 4; ++v) {
                float4 w = __ldg(wp + v);
#pragma unroll
                for (int m = 0; m < 4; ++m) {
                    acc[m][v * 4 + 0] = fmaf(av[u][m], w.x, acc[m][v * 4 + 0]);
                    acc[m][v * 4 + 1] = fmaf(av[u][m], w.y, acc[m][v * 4 + 1]);
                    acc[m][v * 4 + 2] = fmaf(av[u][m], w.z, acc[m][v * 4 + 2]);
                    acc[m][v * 4 + 3] = fmaf(av[u][m], w.w, acc[m][v * 4 + 3]);
                }
            }
        }
    }
    for (int i = CMAIN; i < CIN; ++i) {
        float s0 = in_s[(r + 0)  * PIN + i];
        float s1 = in_s[(r + 8)  * PIN + i];
        float s2 = in_s[(r + 16) * PIN + i];
        float s3 = in_s[(r + 24) * PIN + i];
        const float4* wp = (const float4*)(wbase + i * COUT);
#pragma unroll
        for (int v = 0; v < JW / 4; ++v) {
            float4 w = __ldg(wp + v);
#pragma unroll
            for (int q = 0; q < 4; ++q) {
                acc[0][v * 4 + q] = fmaf(s0, ((const float*)&w)[q], acc[0][v * 4 + q]);
                acc[1][v * 4 + q] = fmaf(s1, ((const float*)&w)[q], acc[1][v * 4 + q]);
                acc[2][v * 4 + q] = fmaf(s2, ((const float*)&w)[q], acc[2][v * 4 + q]);
                acc[3][v * 4 + q] = fmaf(s3, ((const float*)&w)[q], acc[3][v * 4 + q]);
            }
        }
    }
}

template <int COUT>
__device__ __forceinline__ void ln_relu_reg(float acc[4][COUT / 16],
                                            const float* __restrict__ g,
                                            const float* __restrict__ be, int c) {
    constexpr int JW = COUT / 16;
    float gv[JW], bv[JW];
#pragma unroll
    for (int j = 0; j < JW; ++j) { gv[j] = __ldg(g + c * JW + j); bv[j] = __ldg(be + c * JW + j); }
#pragma unroll
    for (int m = 0; m < 4; ++m) {
        float sum = 0.0f;
#pragma unroll
        for (int j = 0; j < JW; ++j) sum += acc[m][j];
        sum += __shfl_xor_sync(0xffffffffu, sum, 1);
        sum += __shfl_xor_sync(0xffffffffu, sum, 2);
        sum += __shfl_xor_sync(0xffffffffu, sum, 4);
        sum += __shfl_xor_sync(0xffffffffu, sum, 8);
        const float mu = sum * (1.0f / COUT);
        float sq = 0.0f;
#pragma unroll
        for (int j = 0; j < JW; ++j) { float d = acc[m][j] - mu; sq += d * d; }
        sq += __shfl_xor_sync(0xffffffffu, sq, 1);
        sq += __shfl_xor_sync(0xffffffffu, sq, 2);
        sq += __shfl_xor_sync(0xffffffffu, sq, 4);
        sq += __shfl_xor_sync(0xffffffffu, sq, 8);
        const float inv = rsqrtf(sq * (1.0f / COUT) + 1e-5f);
#pragma unroll
        for (int j = 0; j < JW; ++j)
            acc[m][j] = fmaxf((acc[m][j] - mu) * inv * gv[j] + bv[j], 0.0f);
    }
}

template <int COUT, int POUT>
__device__ __forceinline__ void store_rows(const float acc[4][COUT / 16],
                                           float* out_s, int c, int r) {
    constexpr int JW = COUT / 16;
#pragma unroll
    for (int m = 0; m < 4; ++m)
#pragma unroll
        for (int v = 0; v < JW / 4; ++v)
            *(float4*)(out_s + (r + 8 * m) * POUT + c * JW + v * 4) =
                make_float4(acc[m][v * 4 + 0], acc[m][v * 4 + 1],
                            acc[m][v * 4 + 2], acc[m][v * 4 + 3]);
}

// ---------------------------------------------------------------------------
// Worker role: NGRP groups of 128 threads, decoupled via named barriers.
// Pacing = one fence-free packed poll on g_cent[b][s].
// ---------------------------------------------------------------------------
__device__ void worker_role(const float* __restrict__ xyz,
                            const float* __restrict__ points,
                            const float* __restrict__ W1, const float* __restrict__ b1,
                            const float* __restrict__ g1, const float* __restrict__ be1,
                            const float* __restrict__ W2, const float* __restrict__ b2,
                            const float* __restrict__ g2, const float* __restrict__ be2,
                            const float* __restrict__ W3, const float* __restrict__ b3,
                            const float* __restrict__ g3, const float* __restrict__ be3,
                            float* __restrict__ new_points,
                            float* smem, int wb, int tid) {
    const int b = wb % BATCH;           // batch
    const int w = wb / BATCH;           // 0..NW_PER_B-1 worker index within batch
    const int grp  = tid >> 7;          // 0..NGRP-1
    const int gtid = tid & 127;
    const int c = gtid & 15;
    const int r = gtid >> 4;
    const int bid = grp + 1;            // named barrier id for this group

    float* sxyz = smem;                         // 12288 floats
    float* gbase = smem + SXYZ_F + grp * GRP_F;
    float* bufA  = gbase;                       // 32*68
    float* bufB  = gbase + 32 * PIN_A;          // 32*132
    int*   sIdx  = (int*)(smem + SXYZ_F + NGRP * GRP_F) + grp * 32;
    float* sCen  = (float*)((int*)(smem + SXYZ_F + NGRP * GRP_F) + NGRP * 32) + grp * 4;

    // stage batch xyz into smem (immutable input) — one block-wide barrier
    {
        const float4* src = (const float4*)(xyz + (size_t)b * NPTS * 3);
        for (int i = tid; i < SXYZ_F / 4; i += THREADS)
            ((float4*)sxyz)[i] = src[i];
    }
    __syncthreads();

    for (int base = w * NGRP; base < NPOINTS; base += NW_PER_B * NGRP) {
        const int s = base + grp;

        // ---- pace on producer: packed centroid+flag, no fences ----
        if (gtid == 0) {
            const float4* cp = &g_cent[b * NPOINTS + s];
            float4 cen = ldcg_v4(cp);
            while (__float_as_int(cen.w) != s + 1) {
                __nanosleep(80);
                cen = ldcg_v4(cp);
            }
            sCen[0] = cen.x; sCen[1] = cen.y; sCen[2] = cen.z;
        }
        bar_grp(bid);

        // ---- ball query: warp 0 of the group ----
        if (gtid < 32) {
            const int lane = gtid;
            const float cx = sCen[0], cy = sCen[1], cz = sCen[2];
            const float R2 = (float)(0.2 * 0.2);
            int cnt = 0, first = -1;
            for (int rr = 0; rr < NPTS / 32; ++rr) {
                int n = rr * 32 + lane;
                float d = sqd_nofma(sxyz[n * 3], sxyz[n * 3 + 1], sxyz[n * 3 + 2],
                                    cx, cy, cz);
                bool ok = !(d > R2);
                unsigned m = __ballot_sync(0xffffffffu, ok);
                if (first < 0 && m) first = rr * 32 + (__ffs(m) - 1);
                if (ok) {
                    int pos = cnt + __popc(m & ((1u << lane) - 1u));
                    if (pos < NSAMPLE) sIdx[pos] = n;
                }
                cnt += __popc(m);
                if (cnt >= NSAMPLE) break;
            }
            if (cnt < NSAMPLE && lane >= cnt && lane < NSAMPLE) sIdx[lane] = first;
        }
        bar_grp(bid);

        // ---- gather: 4 threads per sample ----
        {
            const int k = gtid >> 2, q = gtid & 3;
            const int n = sIdx[k];
            const float4* prow = (const float4*)(points + ((size_t)b * NPTS + n) * 64) + q * 4;
            float* dst = bufA + k * PIN_A + 3 + q * 16;
#pragma unroll
            for (int v = 0; v < 4; ++v) {
                float4 f = __ldg(prow + v);
                dst[v * 4 + 0] = f.x;
                dst[v * 4 + 1] = f.y;
                dst[v * 4 + 2] = f.z;
                dst[v * 4 + 3] = f.w;
            }
            if (q == 0) {
                bufA[k * PIN_A + 0] = sxyz[n * 3 + 0] - sCen[0];
                bufA[k * PIN_A + 1] = sxyz[n * 3 + 1] - sCen[1];
                bufA[k * PIN_A + 2] = sxyz[n * 3 + 2] - sCen[2];
            }
        }
        bar_grp(bid);

        {   // layer 1: 67 -> 64
            float acc[4][4];
            gemm_acc<67, 64, PIN_A>(bufA, W1, b1, acc, c, r);
            ln_relu_reg<64>(acc, g1, be1, c);
            store_rows<64, PIN_B>(acc, bufB, c, r);
        }
        bar_grp(bid);

        {   // layer 2: 64 -> 64
            float acc[4][4];
            gemm_acc<64, 64, PIN_B>(bufB, W2, b2, acc, c, r);
            ln_relu_reg<64>(acc, g2, be2, c);
            store_rows<64, PIN_A>(acc, bufA, c, r);
        }
        bar_grp(bid);

        {   // layer 3: 64 -> 128, fused partial max over 4 samples
            float acc[4][8];
            gemm_acc<64, 128, PIN_A>(bufA, W3, b3, acc, c, r);
            ln_relu_reg<128>(acc, g3, be3, c);
#pragma unroll
            for (int j = 0; j < 8; ++j) {
                float pm = fmaxf(fmaxf(acc[0][j], acc[1][j]), fmaxf(acc[2][j], acc[3][j]));
                bufB[r * PIN_B + c * 8 + j] = pm;
            }
        }
        bar_grp(bid);

        {   // final max over 8 r-partials; relu >= 0 so init 0 exact
            float m = 0.0f;
#pragma unroll
            for (int k = 0; k < 8; ++k) m = fmaxf(m, bufB[k * PIN_B + gtid]);
            new_points[((size_t)b * NPOINTS + s) * 128 + gtid] = m;
        }
        bar_grp(bid);   // protect bufs before next iteration's gather
    }
}

// ---------------------------------------------------------------------------
__global__ __launch_bounds__(THREADS, 1) void fused_kernel(
    const float* __restrict__ xyz, const float* __restrict__ points,
    const float* __restrict__ W1, const float* __restrict__ b1,
    const float* __restrict__ g1, const float* __restrict__ be1,
    const float* __restrict__ W2, const float* __restrict__ b2,
    const float* __restrict__ g2, const float* __restrict__ be2,
    const float* __restrict__ W3, const float* __restrict__ b3,
    const float* __restrict__ g3, const float* __restrict__ be3,
    float* __restrict__ new_xyz, float* __restrict__ new_points) {
    extern __shared__ float smem[];
    const int tid = threadIdx.x;
    if (blockIdx.x < BATCH) {
        fps_role(xyz, new_xyz, blockIdx.x, tid);
    } else {
        worker_role(xyz, points,
                    W1, b1, g1, be1, W2, b2, g2, be2, W3, b3, g3, be3,
                    new_points, smem, blockIdx.x - BATCH, tid);
    }
}

// ---------------------------------------------------------------------------
extern "C" void kernel_launch(void* const* d_in, const int* in_sizes, int n_in,
                              void* d_out, int out_size) {
    (void)in_sizes; (void)n_in; (void)out_size;
    const float* xyz    = (const float*)d_in[0];
    const float* points = (const float*)d_in[1];
    const float* W1  = (const float*)d_in[2];
    const float* b1  = (const float*)d_in[3];
    const float* g1  = (const float*)d_in[4];
    const float* be1 = (const float*)d_in[5];
    const float* W2  = (const float*)d_in[6];
    const float* b2  = (const float*)d_in[7];
    const float* g2  = (const float*)d_in[8];
    const float* be2 = (const float*)d_in[9];
    const float* W3  = (const float*)d_in[10];
    const float* b3  = (const float*)d_in[11];
    const float* g3  = (const float*)d_in[12];
    const float* be3 = (const float*)d_in[13];

    float* out        = (float*)d_out;
    float* new_xyz    = out;                          // [8,1024,3]
    float* new_points = out + BATCH * NPOINTS * 3;    // [8,1024,128]

    cudaFuncSetAttribute(fused_kernel, cudaFuncAttributeMaxDynamicSharedMemorySize,
                         SMEM_DYN);

    reset_kernel<<<BATCH, 1024>>>();
    fused_kernel<<<NBLOCKS, THREADS, SMEM_DYN>>>(xyz, points,
                                                 W1, b1, g1, be1,
                                                 W2, b2, g2, be2,
                                                 W3, b3, g3, be3,
                                                 new_xyz, new_points);
}